// round 1
// baseline (speedup 1.0000x reference)
#include <cuda_runtime.h>
#include <cstdint>

#define DIM    256
#define SLOTS  8
#define NMEM   1000000
#define NB     296            // stream blocks
#define NWRP   (NB * 8)       // warp partials

typedef unsigned long long ull;

// ------------------------- scratch (no allocations allowed) -------------------------
__device__ __align__(256) float g_k[SLOTS * DIM];        // heads*qspace, pre-scaled by log2(e)
__device__ __align__(256) float g_qspace[SLOTS * DIM];   // = rspace
__device__ __align__(256) float g_pacc[(size_t)NWRP * SLOTS * DIM];  // per-warp partial acc
__device__ __align__(256) float g_pl[NWRP * SLOTS];                  // per-warp partial l
__device__ __align__(256) float g_newheads[SLOTS * DIM];
__device__ __align__(256) float g_newstate[DIM];

// ------------------------- packed f32x2 helpers -------------------------
__device__ __forceinline__ ull ffma2(ull a, ull b, ull c) {
    ull d;
    asm("fma.rn.f32x2 %0, %1, %2, %3;" : "=l"(d) : "l"(a), "l"(b), "l"(c));
    return d;
}
__device__ __forceinline__ ull fmul2(ull a, ull b) {
    ull d;
    asm("mul.rn.f32x2 %0, %1, %2;" : "=l"(d) : "l"(a), "l"(b));
    return d;
}
__device__ __forceinline__ ull pack2(float lo, float hi) {
    ull r;
    asm("mov.b64 %0, {%1, %2};" : "=l"(r) : "f"(lo), "f"(hi));
    return r;
}
__device__ __forceinline__ float2 unpack2(ull v) {
    float2 f;
    asm("mov.b64 {%0, %1}, %2;" : "=f"(f.x), "=f"(f.y) : "l"(v));
    return f;
}
__device__ __forceinline__ float ex2f(float x) {
    float r;
    asm("ex2.approx.f32 %0, %1;" : "=f"(r) : "f"(x));
    return r;
}

// ===================================================================================
// Kernel 1: qspace = tanh([state; heads_s] @ qW^T + qb); k = heads*qspace*log2(e)
// grid 256 (one block per output dim d), 128 threads
// ===================================================================================
__global__ void k_setup(const float* __restrict__ heads, const float* __restrict__ state,
                        const float* __restrict__ qW, const float* __restrict__ qb)
{
    const int d = blockIdx.x;
    const int t = threadIdx.x;  // 128 threads
    float pc = 0.f;             // shared state contribution
    float ps[SLOTS];
#pragma unroll
    for (int s = 0; s < SLOTS; s++) ps[s] = 0.f;

    const float* wrow = qW + (size_t)d * (2 * DIM);
    for (int j = t; j < 2 * DIM; j += 128) {
        float w = wrow[j];
        if (j < DIM) {
            pc += w * state[j];
        } else {
            int jj = j - DIM;
#pragma unroll
            for (int s = 0; s < SLOTS; s++) ps[s] += w * heads[s * DIM + jj];
        }
    }

    __shared__ float sm[SLOTS + 1][128];
    sm[SLOTS][t] = pc;
#pragma unroll
    for (int s = 0; s < SLOTS; s++) sm[s][t] = ps[s];
    __syncthreads();
    for (int off = 64; off > 0; off >>= 1) {
        if (t < off) {
#pragma unroll
            for (int s = 0; s <= SLOTS; s++) sm[s][t] += sm[s][t + off];
        }
        __syncthreads();
    }
    if (t < SLOTS) {
        const int s = t;
        float q = tanhf(sm[s][0] + sm[SLOTS][0] + qb[d]);
        g_qspace[s * DIM + d] = q;
        g_k[s * DIM + d] = heads[s * DIM + d] * q * 1.4426950408889634f;  // log2(e)
    }
}

// ===================================================================================
// Kernel 2: the 1 GB stream. warp-per-row, online exp accumulation (no max shift).
// lane covers d in {4*lane..4*lane+3} U {128+4*lane..128+4*lane+3}
// ===================================================================================
__device__ __forceinline__ void process_row(
    ull x0, ull x1, ull x2, ull x3,
    const ull (&k2)[SLOTS][4], ull (&acc2)[SLOTS][4], float& l_local, int lane)
{
    // 8 scores, packed by d-pairs: 8 fmul2 + 24 ffma2
    float p[SLOTS];
#pragma unroll
    for (int s = 0; s < SLOTS; s++) {
        ull q = fmul2(k2[s][0], x0);
        q = ffma2(k2[s][1], x1, q);
        q = ffma2(k2[s][2], x2, q);
        q = ffma2(k2[s][3], x3, q);
        float2 f = unpack2(q);
        p[s] = f.x + f.y;
    }
    // level 1: xor 16 on all 8 (8 shfl)
#pragma unroll
    for (int s = 0; s < SLOTS; s++) p[s] += __shfl_xor_sync(0xffffffffu, p[s], 16);
    // split: low half owns slots 0-3, high half slots 4-7 (4 SEL)
    const bool hi = (lane >= 16);
    float a0 = hi ? p[4] : p[0];
    float a1 = hi ? p[5] : p[1];
    float a2 = hi ? p[6] : p[2];
    float a3 = hi ? p[7] : p[3];
    // 4 more levels on 4 values (16 shfl)
#pragma unroll
    for (int dlt = 8; dlt >= 1; dlt >>= 1) {
        a0 += __shfl_xor_sync(0xffffffffu, a0, dlt);
        a1 += __shfl_xor_sync(0xffffffffu, a1, dlt);
        a2 += __shfl_xor_sync(0xffffffffu, a2, dlt);
        a3 += __shfl_xor_sync(0xffffffffu, a3, dlt);
    }
    // each lane exps one slot: slot = (hi?4:0) + (lane&3)   (3 SEL + 1 MUFU)
    float t01 = (lane & 1) ? a1 : a0;
    float t23 = (lane & 1) ? a3 : a2;
    float tt  = (lane & 2) ? t23 : t01;
    float wl = ex2f(tt);          // k pre-scaled by log2e -> this is exp(score)
    l_local += wl;                // lanes 0-3 / 16-19 hold the live copies
    // gather all 8 slot weights (8 shfl, constant source lanes)
    float w[SLOTS];
    w[0] = __shfl_sync(0xffffffffu, wl, 0);
    w[1] = __shfl_sync(0xffffffffu, wl, 1);
    w[2] = __shfl_sync(0xffffffffu, wl, 2);
    w[3] = __shfl_sync(0xffffffffu, wl, 3);
    w[4] = __shfl_sync(0xffffffffu, wl, 16);
    w[5] = __shfl_sync(0xffffffffu, wl, 17);
    w[6] = __shfl_sync(0xffffffffu, wl, 18);
    w[7] = __shfl_sync(0xffffffffu, wl, 19);
    // acc update: 8 packs + 32 ffma2
#pragma unroll
    for (int s = 0; s < SLOTS; s++) {
        ull w2 = pack2(w[s], w[s]);
        acc2[s][0] = ffma2(w2, x0, acc2[s][0]);
        acc2[s][1] = ffma2(w2, x1, acc2[s][1]);
        acc2[s][2] = ffma2(w2, x2, acc2[s][2]);
        acc2[s][3] = ffma2(w2, x3, acc2[s][3]);
    }
}

__global__ void __launch_bounds__(256, 1) k_stream(const float* __restrict__ memory)
{
    const int lane = threadIdx.x & 31;
    const int warp = threadIdx.x >> 5;
    const int b = blockIdx.x;
    const int r0 = (int)(((long long)NMEM * b) / NB);
    const int r1 = (int)(((long long)NMEM * (b + 1)) / NB);

    // per-lane k slices -> registers (pairs match the x layout)
    ull k2[SLOTS][4];
#pragma unroll
    for (int s = 0; s < SLOTS; s++) {
        ulonglong2 ka = *(const ulonglong2*)(g_k + s * DIM + 4 * lane);
        ulonglong2 kb = *(const ulonglong2*)(g_k + s * DIM + 128 + 4 * lane);
        k2[s][0] = ka.x; k2[s][1] = ka.y; k2[s][2] = kb.x; k2[s][3] = kb.y;
    }
    ull acc2[SLOTS][4];
#pragma unroll
    for (int s = 0; s < SLOTS; s++) {
        acc2[s][0] = 0ull; acc2[s][1] = 0ull; acc2[s][2] = 0ull; acc2[s][3] = 0ull;
    }
    float l_local = 0.f;

    const int first = r0 + warp;
    int cnt = (first < r1) ? ((r1 - first + 7) >> 3) : 0;

    const ulonglong2* base0 = (const ulonglong2*)(memory + (size_t)first * DIM) + lane;
    // row(i) = first + 8*i  ->  base0 + i * (8*64) ull2  (64 ull2 per row)
    ulonglong2 A0, A1, B0, B1, NA0, NA1, NB0, NB1;
    A0 = A1 = B0 = B1 = NA0 = NA1 = NB0 = NB1 = make_ulonglong2(0ull, 0ull);
    if (cnt > 0) { const ulonglong2* p = base0;       A0 = __ldcs(p); A1 = __ldcs(p + 32); }
    if (cnt > 1) { const ulonglong2* p = base0 + 512; B0 = __ldcs(p); B1 = __ldcs(p + 32); }

    for (int i = 0; i < cnt; i += 2) {
        if (i + 2 < cnt) { const ulonglong2* p = base0 + (size_t)(i + 2) * 512; NA0 = __ldcs(p); NA1 = __ldcs(p + 32); }
        if (i + 3 < cnt) { const ulonglong2* p = base0 + (size_t)(i + 3) * 512; NB0 = __ldcs(p); NB1 = __ldcs(p + 32); }
        process_row(A0.x, A0.y, A1.x, A1.y, k2, acc2, l_local, lane);
        if (i + 1 < cnt)
            process_row(B0.x, B0.y, B1.x, B1.y, k2, acc2, l_local, lane);
        A0 = NA0; A1 = NA1; B0 = NB0; B1 = NB1;
    }

    // writeout per-warp partials
    const int wb = b * 8 + warp;
    float* dst = g_pacc + (size_t)wb * (SLOTS * DIM);
#pragma unroll
    for (int s = 0; s < SLOTS; s++) {
        float2 u0 = unpack2(acc2[s][0]);
        float2 u1 = unpack2(acc2[s][1]);
        float2 u2 = unpack2(acc2[s][2]);
        float2 u3 = unpack2(acc2[s][3]);
        float4 v0 = make_float4(u0.x, u0.y, u1.x, u1.y);
        float4 v1 = make_float4(u2.x, u2.y, u3.x, u3.y);
        *(float4*)(dst + s * DIM + 4 * lane) = v0;
        *(float4*)(dst + s * DIM + 128 + 4 * lane) = v1;
    }
    if (lane < 4)                    g_pl[wb * SLOTS + lane] = l_local;
    else if (lane >= 16 && lane < 20) g_pl[wb * SLOTS + 4 + (lane - 16)] = l_local;
}

// ===================================================================================
// Kernel 3: reduce partials, compute new_heads.  grid 16 x 128 = 2048 threads
// ===================================================================================
__global__ void k_reduce(const float* __restrict__ heads)
{
    const int e = blockIdx.x * 128 + threadIdx.x;  // 0..2047  (= s*256 + d)
    const int s = e >> 8;
    float acc = 0.f;
    for (int wb = 0; wb < NWRP; wb++) acc += g_pacc[(size_t)wb * (SLOTS * DIM) + e];
    float l = 0.f;
    for (int wb = 0; wb < NWRP; wb++) l += g_pl[wb * SLOTS + s];  // warp-broadcast reads
    float raw = acc / l;
    float q = g_qspace[e];
    g_newheads[e] = raw * q + (1.f - q) * heads[e];
}

// ===================================================================================
// Kernel 4: new_state = [state; new_heads] @ sW^T + sb.  grid 256 (one per output i)
// ===================================================================================
__global__ void k_synth(const float* __restrict__ state, const float* __restrict__ sW,
                        const float* __restrict__ sb)
{
    const int i = blockIdx.x;
    const int t = threadIdx.x;  // 256
    const float* w = sW + (size_t)i * (DIM * (SLOTS + 1));
    float p = 0.f;
#pragma unroll
    for (int j = t; j < DIM * (SLOTS + 1); j += 256) {
        float c = (j < DIM) ? state[j] : g_newheads[j - DIM];
        p += w[j] * c;
    }
    __shared__ float sm[256];
    sm[t] = p;
    __syncthreads();
    for (int off = 128; off > 0; off >>= 1) {
        if (t < off) sm[t] += sm[t + off];
        __syncthreads();
    }
    if (t == 0) g_newstate[i] = sm[0] + sb[i];
}

// ===================================================================================
// Kernel 5: reveal = sigmoid(new_state @ rvW^T + rvb); out = new_state * reveal
// ===================================================================================
__global__ void k_out(const float* __restrict__ rvW, const float* __restrict__ rvb,
                      float* __restrict__ out)
{
    const int t = threadIdx.x;  // 256
    float ns = g_newstate[t];
    __shared__ float sm[256];
    sm[t] = ns * rvW[t];
    __syncthreads();
    for (int off = 128; off > 0; off >>= 1) {
        if (t < off) sm[t] += sm[t + off];
        __syncthreads();
    }
    __shared__ float rev;
    if (t == 0) {
        float z = sm[0] + rvb[0];
        rev = 1.f / (1.f + __expf(-z));
    }
    __syncthreads();
    out[t] = ns * rev;
}

// ===================================================================================
extern "C" void kernel_launch(void* const* d_in, const int* in_sizes, int n_in,
                              void* d_out, int out_size)
{
    const float* memory = (const float*)d_in[0];
    const float* heads  = (const float*)d_in[1];
    const float* state  = (const float*)d_in[2];
    const float* qW     = (const float*)d_in[3];
    const float* qb     = (const float*)d_in[4];
    const float* sW     = (const float*)d_in[5];
    const float* sb     = (const float*)d_in[6];
    const float* rvW    = (const float*)d_in[7];
    const float* rvb    = (const float*)d_in[8];
    float* out = (float*)d_out;

    k_setup<<<DIM, 128>>>(heads, state, qW, qb);
    k_stream<<<NB, 256>>>(memory);
    k_reduce<<<16, 128>>>(heads);
    k_synth<<<DIM, 256>>>(state, sW, sb);
    k_out<<<1, 256>>>(rvW, rvb, out);
}

// round 2
// speedup vs baseline: 1.1777x; 1.1777x over previous
#include <cuda_runtime.h>
#include <cstdint>

#define DIM     256
#define SLOTS   8
#define NMEM    1000000
#define NCTA    148
#define WARPS   12
#define THREADS 384
#define TROWS   48                      // rows per tile (4 per warp)
#define STAGES  4
#define TILE_BYTES  (TROWS * DIM * 4)   // 49152
#define TILES_BYTES (STAGES * TILE_BYTES)
#define DYN_SMEM    (TILES_BYTES + 128) // + barriers

typedef unsigned long long ull;

// ------------------------- scratch (no allocations allowed) -------------------------
__device__ __align__(256) float g_k[SLOTS * DIM];          // heads*qspace * log2(e)
__device__ __align__(256) float g_qspace[SLOTS * DIM];
__device__ __align__(256) float g_pacc[NCTA * SLOTS * DIM];// per-CTA partial acc
__device__ __align__(256) float g_pl[NCTA * SLOTS];        // per-CTA partial l
__device__ __align__(256) float g_newheads[SLOTS * DIM];
__device__ __align__(256) float g_newstate[DIM];

// ------------------------- helpers -------------------------
__device__ __forceinline__ ull ffma2(ull a, ull b, ull c) {
    ull d; asm("fma.rn.f32x2 %0, %1, %2, %3;" : "=l"(d) : "l"(a), "l"(b), "l"(c)); return d;
}
__device__ __forceinline__ ull fmul2(ull a, ull b) {
    ull d; asm("mul.rn.f32x2 %0, %1, %2;" : "=l"(d) : "l"(a), "l"(b)); return d;
}
__device__ __forceinline__ ull pack2(float lo, float hi) {
    ull r; asm("mov.b64 %0, {%1, %2};" : "=l"(r) : "f"(lo), "f"(hi)); return r;
}
__device__ __forceinline__ float2 unpack2(ull v) {
    float2 f; asm("mov.b64 {%0, %1}, %2;" : "=f"(f.x), "=f"(f.y) : "l"(v)); return f;
}
__device__ __forceinline__ float ex2f(float x) {
    float r; asm("ex2.approx.f32 %0, %1;" : "=f"(r) : "f"(x)); return r;
}
__device__ __forceinline__ uint32_t smem_u32(const void* p) {
    uint32_t a;
    asm("{ .reg .u64 t; cvta.to.shared.u64 t, %1; cvt.u32.u64 %0, t; }" : "=r"(a) : "l"(p));
    return a;
}
__device__ __forceinline__ void mbar_init(uint32_t a, uint32_t cnt) {
    asm volatile("mbarrier.init.shared.b64 [%0], %1;" :: "r"(a), "r"(cnt) : "memory");
}
__device__ __forceinline__ void mbar_expect_tx(uint32_t a, uint32_t bytes) {
    asm volatile("mbarrier.arrive.expect_tx.shared.b64 _, [%0], %1;" :: "r"(a), "r"(bytes) : "memory");
}
__device__ __forceinline__ void mbar_arrive(uint32_t a) {
    asm volatile("mbarrier.arrive.shared.b64 _, [%0];" :: "r"(a) : "memory");
}
__device__ __forceinline__ void mbar_wait(uint32_t a, uint32_t parity) {
    asm volatile(
        "{\n\t.reg .pred P;\n"
        "WL%=:\n\t"
        "mbarrier.try_wait.parity.acquire.cta.shared::cta.b64 P, [%0], %1, 0x989680;\n\t"
        "@P bra.uni WD%=;\n\t"
        "bra.uni WL%=;\n"
        "WD%=:\n\t}"
        :: "r"(a), "r"(parity) : "memory");
}
__device__ __forceinline__ void bulk_g2s(uint32_t dst, const void* src, uint32_t bytes, uint32_t mbar) {
    asm volatile(
        "cp.async.bulk.shared::cta.global.mbarrier::complete_tx::bytes [%0], [%1], %2, [%3];"
        :: "r"(dst), "l"(src), "r"(bytes), "r"(mbar) : "memory");
}

// ===================================================================================
// Kernel 1: qspace = tanh([state; heads_s] @ qW^T + qb); k = heads*qspace*log2(e)
// ===================================================================================
__global__ void k_setup(const float* __restrict__ heads, const float* __restrict__ state,
                        const float* __restrict__ qW, const float* __restrict__ qb)
{
    const int d = blockIdx.x;
    const int t = threadIdx.x;  // 128 threads
    float pc = 0.f;
    float ps[SLOTS];
#pragma unroll
    for (int s = 0; s < SLOTS; s++) ps[s] = 0.f;

    const float* wrow = qW + (size_t)d * (2 * DIM);
    for (int j = t; j < 2 * DIM; j += 128) {
        float w = wrow[j];
        if (j < DIM) {
            pc += w * state[j];
        } else {
            int jj = j - DIM;
#pragma unroll
            for (int s = 0; s < SLOTS; s++) ps[s] += w * heads[s * DIM + jj];
        }
    }

    __shared__ float sm[SLOTS + 1][128];
    sm[SLOTS][t] = pc;
#pragma unroll
    for (int s = 0; s < SLOTS; s++) sm[s][t] = ps[s];
    __syncthreads();
    for (int off = 64; off > 0; off >>= 1) {
        if (t < off) {
#pragma unroll
            for (int s = 0; s <= SLOTS; s++) sm[s][t] += sm[s][t + off];
        }
        __syncthreads();
    }
    if (t < SLOTS) {
        const int s = t;
        float q = tanhf(sm[s][0] + sm[SLOTS][0] + qb[d]);
        g_qspace[s * DIM + d] = q;
        g_k[s * DIM + d] = heads[s * DIM + d] * q * 1.4426950408889634f;
    }
}

// ===================================================================================
// Kernel 2: the 1 GB stream. cp.async.bulk producer -> smem ring, 12 consumer warps.
// ===================================================================================
__device__ __forceinline__ void process_row(
    ull x0, ull x1, ull x2, ull x3,
    const ull (&k2)[SLOTS][4], ull (&acc2)[SLOTS][4], float& l_local, int lane)
{
    // scores: 8 fmul2 + 24 ffma2
    float p[SLOTS];
#pragma unroll
    for (int s = 0; s < SLOTS; s++) {
        ull q = fmul2(k2[s][0], x0);
        q = ffma2(k2[s][1], x1, q);
        q = ffma2(k2[s][2], x2, q);
        q = ffma2(k2[s][3], x3, q);
        float2 f = unpack2(q);
        p[s] = f.x + f.y;
    }
    // progressive-split reduction: 16 shfl + 7 sel
#pragma unroll
    for (int s = 0; s < SLOTS; s++) p[s] += __shfl_xor_sync(0xffffffffu, p[s], 16);
    const bool b4 = (lane & 16);
    float a0 = b4 ? p[4] : p[0];
    float a1 = b4 ? p[5] : p[1];
    float a2 = b4 ? p[6] : p[2];
    float a3 = b4 ? p[7] : p[3];
    a0 += __shfl_xor_sync(0xffffffffu, a0, 8);
    a1 += __shfl_xor_sync(0xffffffffu, a1, 8);
    a2 += __shfl_xor_sync(0xffffffffu, a2, 8);
    a3 += __shfl_xor_sync(0xffffffffu, a3, 8);
    const bool b3 = (lane & 8);
    float c0 = b3 ? a2 : a0;
    float c1 = b3 ? a3 : a1;
    c0 += __shfl_xor_sync(0xffffffffu, c0, 4);
    c1 += __shfl_xor_sync(0xffffffffu, c1, 4);
    const bool b2 = (lane & 4);
    float d0 = b2 ? c1 : c0;
    d0 += __shfl_xor_sync(0xffffffffu, d0, 2);
    d0 += __shfl_xor_sync(0xffffffffu, d0, 1);
    // lane 4*s (plus 3 copies) now holds score for slot s = 4*bit4+2*bit3+bit2
    float wl = ex2f(d0);
    l_local += ((lane & 3) == 0) ? wl : 0.f;
    // broadcast the 8 weights (8 shfl)
    float w[SLOTS];
#pragma unroll
    for (int s = 0; s < SLOTS; s++) w[s] = __shfl_sync(0xffffffffu, wl, s * 4);
    // acc: 8 pack + 32 ffma2
#pragma unroll
    for (int s = 0; s < SLOTS; s++) {
        ull w2 = pack2(w[s], w[s]);
        acc2[s][0] = ffma2(w2, x0, acc2[s][0]);
        acc2[s][1] = ffma2(w2, x1, acc2[s][1]);
        acc2[s][2] = ffma2(w2, x2, acc2[s][2]);
        acc2[s][3] = ffma2(w2, x3, acc2[s][3]);
    }
}

__global__ void __launch_bounds__(THREADS, 1) k_stream(const float* __restrict__ memory)
{
    extern __shared__ char smem[];
    const int tid  = threadIdx.x;
    const int lane = tid & 31;
    const int warp = tid >> 5;
    const int c = blockIdx.x;
    const int r0 = (int)(((long long)NMEM * c) / NCTA);
    const int r1 = (int)(((long long)NMEM * (c + 1)) / NCTA);
    const int T  = (r1 - r0 + TROWS - 1) / TROWS;

    const uint32_t sb     = smem_u32(smem);
    const uint32_t fullb  = sb + TILES_BYTES;       // full[i]  @ +8*i
    const uint32_t emptyb = fullb + 32;             // empty[i] @ +8*i

    if (tid == 0) {
#pragma unroll
        for (int i = 0; i < STAGES; i++) {
            mbar_init(fullb + 8 * i, 1);
            mbar_init(emptyb + 8 * i, WARPS);
        }
    }
    __syncthreads();

    // k slices -> registers
    ull k2[SLOTS][4];
#pragma unroll
    for (int s = 0; s < SLOTS; s++) {
        ulonglong2 ka = *(const ulonglong2*)(g_k + s * DIM + 4 * lane);
        ulonglong2 kb = *(const ulonglong2*)(g_k + s * DIM + 128 + 4 * lane);
        k2[s][0] = ka.x; k2[s][1] = ka.y; k2[s][2] = kb.x; k2[s][3] = kb.y;
    }
    ull acc2[SLOTS][4];
#pragma unroll
    for (int s = 0; s < SLOTS; s++) {
        acc2[s][0] = 0ull; acc2[s][1] = 0ull; acc2[s][2] = 0ull; acc2[s][3] = 0ull;
    }
    float l_local = 0.f;

    // producer primes the ring
    if (tid == 0) {
        int n0 = (T < STAGES) ? T : STAGES;
        for (int t = 0; t < n0; t++) {
            int ts   = r0 + t * TROWS;
            int rows = (r1 - ts < TROWS) ? (r1 - ts) : TROWS;
            uint32_t bytes = (uint32_t)rows * (DIM * 4);
            mbar_expect_tx(fullb + 8 * t, bytes);
            bulk_g2s(sb + t * TILE_BYTES, memory + (size_t)ts * DIM, bytes, fullb + 8 * t);
        }
    }

    unsigned fmask = 0, emask = 0;
    for (int t = 0; t < T; t++) {
        const int st = t & (STAGES - 1);
        mbar_wait(fullb + 8 * st, (fmask >> st) & 1u);
        fmask ^= 1u << st;

        const int tstart = r0 + t * TROWS;
        const char* tile = smem + st * TILE_BYTES;
#pragma unroll
        for (int i = 0; i < 4; i++) {
            const int rl = warp * 4 + i;
            if (tstart + rl < r1) {
                const ulonglong2* xp = (const ulonglong2*)(tile + rl * (DIM * 4)) + lane;
                ulonglong2 A = xp[0];
                ulonglong2 B = xp[32];
                process_row(A.x, A.y, B.x, B.y, k2, acc2, l_local, lane);
            }
        }
        __syncwarp();
        if (lane == 0) mbar_arrive(emptyb + 8 * st);

        if (tid == 0 && t + STAGES < T) {
            mbar_wait(emptyb + 8 * st, (emask >> st) & 1u);
            emask ^= 1u << st;
            int t2   = t + STAGES;
            int ts   = r0 + t2 * TROWS;
            int rows = (r1 - ts < TROWS) ? (r1 - ts) : TROWS;
            uint32_t bytes = (uint32_t)rows * (DIM * 4);
            mbar_expect_tx(fullb + 8 * st, bytes);
            bulk_g2s(sb + st * TILE_BYTES, memory + (size_t)ts * DIM, bytes, fullb + 8 * st);
        }
    }

    // ---------------- per-CTA reduction (reuse ring smem) ----------------
    __syncthreads();
    float* sred = (float*)smem;                       // [WARPS][2048]
    float* sl   = (float*)(smem + WARPS * 2048 * 4);  // [WARPS][8]
#pragma unroll
    for (int s = 0; s < SLOTS; s++) {
        float2 u0 = unpack2(acc2[s][0]);
        float2 u1 = unpack2(acc2[s][1]);
        float2 u2 = unpack2(acc2[s][2]);
        float2 u3 = unpack2(acc2[s][3]);
        *(float4*)(sred + warp * 2048 + s * DIM + 4 * lane)       = make_float4(u0.x, u0.y, u1.x, u1.y);
        *(float4*)(sred + warp * 2048 + s * DIM + 128 + 4 * lane) = make_float4(u2.x, u2.y, u3.x, u3.y);
    }
    if ((lane & 3) == 0) sl[warp * 8 + (lane >> 2)] = l_local;
    __syncthreads();

    for (int e = tid; e < 2048; e += THREADS) {
        float sum = 0.f;
#pragma unroll
        for (int w = 0; w < WARPS; w++) sum += sred[w * 2048 + e];
        g_pacc[c * 2048 + e] = sum;
    }
    if (tid < 8) {
        float sum = 0.f;
#pragma unroll
        for (int w = 0; w < WARPS; w++) sum += sl[w * 8 + tid];
        g_pl[c * 8 + tid] = sum;
    }
}

// ===================================================================================
// Kernel 3: reduce per-CTA partials, compute new_heads. 16 x 128 threads
// ===================================================================================
__global__ void k_reduce(const float* __restrict__ heads)
{
    const int e = blockIdx.x * 128 + threadIdx.x;  // 0..2047 (= s*256 + d)
    const int s = e >> 8;
    float acc = 0.f, l = 0.f;
    for (int p = 0; p < NCTA; p++) {
        acc += g_pacc[p * 2048 + e];
        l   += g_pl[p * 8 + s];
    }
    float raw = acc / l;
    float q = g_qspace[e];
    g_newheads[e] = raw * q + (1.f - q) * heads[e];
}

// ===================================================================================
// Kernel 4: new_state = [state; new_heads] @ sW^T + sb. grid 256 x 128 thr, float4
// ===================================================================================
__global__ void k_synth(const float* __restrict__ state, const float* __restrict__ sW,
                        const float* __restrict__ sb)
{
    const int i = blockIdx.x;
    const int t = threadIdx.x;  // 128
    const float4* w4 = (const float4*)(sW + (size_t)i * (DIM * (SLOTS + 1)));
    float p = 0.f;
#pragma unroll
    for (int j4 = t; j4 < (DIM * (SLOTS + 1)) / 4; j4 += 128) {
        float4 w = w4[j4];
        float4 cv;
        if (j4 < DIM / 4) cv = *(const float4*)(state + 4 * j4);
        else              cv = *(const float4*)(g_newheads + 4 * j4 - DIM);
        p += w.x * cv.x + w.y * cv.y + w.z * cv.z + w.w * cv.w;
    }
    __shared__ float sm[128];
    sm[t] = p;
    __syncthreads();
    for (int off = 64; off > 0; off >>= 1) {
        if (t < off) sm[t] += sm[t + off];
        __syncthreads();
    }
    if (t == 0) g_newstate[i] = sm[0] + sb[i];
}

// ===================================================================================
// Kernel 5: reveal = sigmoid(new_state @ rvW^T + rvb); out = new_state * reveal
// ===================================================================================
__global__ void k_out(const float* __restrict__ rvW, const float* __restrict__ rvb,
                      float* __restrict__ out)
{
    const int t = threadIdx.x;  // 256
    float ns = g_newstate[t];
    __shared__ float sm[256];
    sm[t] = ns * rvW[t];
    __syncthreads();
    for (int off = 128; off > 0; off >>= 1) {
        if (t < off) sm[t] += sm[t + off];
        __syncthreads();
    }
    __shared__ float rev;
    if (t == 0) {
        float z = sm[0] + rvb[0];
        rev = 1.f / (1.f + __expf(-z));
    }
    __syncthreads();
    out[t] = ns * rev;
}

// ===================================================================================
extern "C" void kernel_launch(void* const* d_in, const int* in_sizes, int n_in,
                              void* d_out, int out_size)
{
    const float* memory = (const float*)d_in[0];
    const float* heads  = (const float*)d_in[1];
    const float* state  = (const float*)d_in[2];
    const float* qW     = (const float*)d_in[3];
    const float* qb     = (const float*)d_in[4];
    const float* sW     = (const float*)d_in[5];
    const float* sb     = (const float*)d_in[6];
    const float* rvW    = (const float*)d_in[7];
    const float* rvb    = (const float*)d_in[8];
    float* out = (float*)d_out;

    cudaFuncSetAttribute(k_stream, cudaFuncAttributeMaxDynamicSharedMemorySize, DYN_SMEM);

    k_setup<<<DIM, 128>>>(heads, state, qW, qb);
    k_stream<<<NCTA, THREADS, DYN_SMEM>>>(memory);
    k_reduce<<<16, 128>>>(heads);
    k_synth<<<DIM, 128>>>(state, sW, sb);
    k_out<<<1, 256>>>(rvW, rvb, out);
}

// round 3
// speedup vs baseline: 1.3021x; 1.1056x over previous
#include <cuda_runtime.h>
#include <cstdint>

#define DIM     256
#define SLOTS   8
#define NMEM    1000000
#define NCTA    148
#define CWARPS  11                      // consumer warps
#define THREADS 384                     // 11 consumers + 1 producer warp
#define PROD_WARP 11
#define TROWS   44                      // rows per tile (4 per consumer warp)
#define STAGES  4
#define TILE_BYTES  (TROWS * DIM * 4)   // 45056
#define TILES_BYTES (STAGES * TILE_BYTES)
#define DYN_SMEM    (TILES_BYTES + 128)

typedef unsigned long long ull;

// ------------------------- scratch (no allocations allowed) -------------------------
__device__ __align__(256) float g_k[SLOTS * DIM];          // heads*qspace * log2(e)
__device__ __align__(256) float g_qspace[SLOTS * DIM];
__device__ __align__(256) float g_pacc[NCTA * SLOTS * DIM];// per-CTA partial acc
__device__ __align__(256) float g_pl[NCTA * SLOTS];        // per-CTA partial l
__device__ __align__(256) float g_newheads[SLOTS * DIM];
__device__ __align__(256) float g_newstate[DIM];

// ------------------------- helpers -------------------------
__device__ __forceinline__ ull ffma2(ull a, ull b, ull c) {
    ull d; asm("fma.rn.f32x2 %0, %1, %2, %3;" : "=l"(d) : "l"(a), "l"(b), "l"(c)); return d;
}
__device__ __forceinline__ ull fmul2(ull a, ull b) {
    ull d; asm("mul.rn.f32x2 %0, %1, %2;" : "=l"(d) : "l"(a), "l"(b)); return d;
}
__device__ __forceinline__ ull pack2(float lo, float hi) {
    ull r; asm("mov.b64 %0, {%1, %2};" : "=l"(r) : "f"(lo), "f"(hi)); return r;
}
__device__ __forceinline__ float2 unpack2(ull v) {
    float2 f; asm("mov.b64 {%0, %1}, %2;" : "=f"(f.x), "=f"(f.y) : "l"(v)); return f;
}
__device__ __forceinline__ float ex2f(float x) {
    float r; asm("ex2.approx.f32 %0, %1;" : "=f"(r) : "f"(x)); return r;
}
__device__ __forceinline__ uint32_t smem_u32(const void* p) {
    uint32_t a;
    asm("{ .reg .u64 t; cvta.to.shared.u64 t, %1; cvt.u32.u64 %0, t; }" : "=r"(a) : "l"(p));
    return a;
}
__device__ __forceinline__ void mbar_init(uint32_t a, uint32_t cnt) {
    asm volatile("mbarrier.init.shared.b64 [%0], %1;" :: "r"(a), "r"(cnt) : "memory");
}
__device__ __forceinline__ void mbar_expect_tx(uint32_t a, uint32_t bytes) {
    asm volatile("mbarrier.arrive.expect_tx.shared.b64 _, [%0], %1;" :: "r"(a), "r"(bytes) : "memory");
}
__device__ __forceinline__ void mbar_arrive(uint32_t a) {
    asm volatile("mbarrier.arrive.shared.b64 _, [%0];" :: "r"(a) : "memory");
}
__device__ __forceinline__ void mbar_wait(uint32_t a, uint32_t parity) {
    asm volatile(
        "{\n\t.reg .pred P;\n"
        "WL%=:\n\t"
        "mbarrier.try_wait.parity.acquire.cta.shared::cta.b64 P, [%0], %1, 0x989680;\n\t"
        "@P bra.uni WD%=;\n\t"
        "bra.uni WL%=;\n"
        "WD%=:\n\t}"
        :: "r"(a), "r"(parity) : "memory");
}
__device__ __forceinline__ void bulk_g2s(uint32_t dst, const void* src, uint32_t bytes, uint32_t mbar) {
    asm volatile(
        "cp.async.bulk.shared::cta.global.mbarrier::complete_tx::bytes [%0], [%1], %2, [%3];"
        :: "r"(dst), "l"(src), "r"(bytes), "r"(mbar) : "memory");
}

// ===================================================================================
// Kernel 1: qspace = tanh([state; heads_s] @ qW^T + qb); k = heads*qspace*log2(e)
// ===================================================================================
__global__ void k_setup(const float* __restrict__ heads, const float* __restrict__ state,
                        const float* __restrict__ qW, const float* __restrict__ qb)
{
    const int d = blockIdx.x;
    const int t = threadIdx.x;  // 128 threads
    float pc = 0.f;
    float ps[SLOTS];
#pragma unroll
    for (int s = 0; s < SLOTS; s++) ps[s] = 0.f;

    const float* wrow = qW + (size_t)d * (2 * DIM);
    for (int j = t; j < 2 * DIM; j += 128) {
        float w = wrow[j];
        if (j < DIM) {
            pc += w * state[j];
        } else {
            int jj = j - DIM;
#pragma unroll
            for (int s = 0; s < SLOTS; s++) ps[s] += w * heads[s * DIM + jj];
        }
    }

    __shared__ float sm[SLOTS + 1][128];
    sm[SLOTS][t] = pc;
#pragma unroll
    for (int s = 0; s < SLOTS; s++) sm[s][t] = ps[s];
    __syncthreads();
    for (int off = 64; off > 0; off >>= 1) {
        if (t < off) {
#pragma unroll
            for (int s = 0; s <= SLOTS; s++) sm[s][t] += sm[s][t + off];
        }
        __syncthreads();
    }
    if (t < SLOTS) {
        const int s = t;
        float q = tanhf(sm[s][0] + sm[SLOTS][0] + qb[d]);
        g_qspace[s * DIM + d] = q;
        g_k[s * DIM + d] = heads[s * DIM + d] * q * 1.4426950408889634f;
    }
}

// ===================================================================================
// Kernel 2: the 1 GB stream. Warp-specialized: warp 11 = cp.async.bulk producer,
// warps 0-10 = consumers (4 rows each per 44-row tile).
// ===================================================================================
__device__ __forceinline__ void process_row(
    ull x0, ull x1, ull x2, ull x3,
    const ull (&k2)[SLOTS][4], ull (&acc2)[SLOTS][4], float& l_local, int lane)
{
    // scores: 8 fmul2 + 24 ffma2
    float p[SLOTS];
#pragma unroll
    for (int s = 0; s < SLOTS; s++) {
        ull q = fmul2(k2[s][0], x0);
        q = ffma2(k2[s][1], x1, q);
        q = ffma2(k2[s][2], x2, q);
        q = ffma2(k2[s][3], x3, q);
        float2 f = unpack2(q);
        p[s] = f.x + f.y;
    }
    // progressive-split reduction: 16 shfl + 7 sel
#pragma unroll
    for (int s = 0; s < SLOTS; s++) p[s] += __shfl_xor_sync(0xffffffffu, p[s], 16);
    const bool b4 = (lane & 16);
    float a0 = b4 ? p[4] : p[0];
    float a1 = b4 ? p[5] : p[1];
    float a2 = b4 ? p[6] : p[2];
    float a3 = b4 ? p[7] : p[3];
    a0 += __shfl_xor_sync(0xffffffffu, a0, 8);
    a1 += __shfl_xor_sync(0xffffffffu, a1, 8);
    a2 += __shfl_xor_sync(0xffffffffu, a2, 8);
    a3 += __shfl_xor_sync(0xffffffffu, a3, 8);
    const bool b3 = (lane & 8);
    float c0 = b3 ? a2 : a0;
    float c1 = b3 ? a3 : a1;
    c0 += __shfl_xor_sync(0xffffffffu, c0, 4);
    c1 += __shfl_xor_sync(0xffffffffu, c1, 4);
    const bool b2 = (lane & 4);
    float d0 = b2 ? c1 : c0;
    d0 += __shfl_xor_sync(0xffffffffu, d0, 2);
    d0 += __shfl_xor_sync(0xffffffffu, d0, 1);
    // lane 4*s (plus 3 copies) holds score for slot s = 4*bit4+2*bit3+bit2
    float wl = ex2f(d0);
    l_local += ((lane & 3) == 0) ? wl : 0.f;
    float w[SLOTS];
#pragma unroll
    for (int s = 0; s < SLOTS; s++) w[s] = __shfl_sync(0xffffffffu, wl, s * 4);
#pragma unroll
    for (int s = 0; s < SLOTS; s++) {
        ull w2 = pack2(w[s], w[s]);
        acc2[s][0] = ffma2(w2, x0, acc2[s][0]);
        acc2[s][1] = ffma2(w2, x1, acc2[s][1]);
        acc2[s][2] = ffma2(w2, x2, acc2[s][2]);
        acc2[s][3] = ffma2(w2, x3, acc2[s][3]);
    }
}

__global__ void __launch_bounds__(THREADS, 1) k_stream(const float* __restrict__ memory)
{
    extern __shared__ char smem[];
    const int tid  = threadIdx.x;
    const int lane = tid & 31;
    const int warp = tid >> 5;
    const int c = blockIdx.x;
    const int r0 = (int)(((long long)NMEM * c) / NCTA);
    const int r1 = (int)(((long long)NMEM * (c + 1)) / NCTA);
    const int T  = (r1 - r0 + TROWS - 1) / TROWS;

    const uint32_t sb     = smem_u32(smem);
    const uint32_t fullb  = sb + TILES_BYTES;       // full[i]  @ +8*i
    const uint32_t emptyb = fullb + 32;             // empty[i] @ +8*i

    if (tid == 0) {
#pragma unroll
        for (int i = 0; i < STAGES; i++) {
            mbar_init(fullb + 8 * i, 1);
            mbar_init(emptyb + 8 * i, CWARPS);
        }
    }
    __syncthreads();

    if (warp == PROD_WARP) {
        // -------- producer warp: only lane 0 drives the ring --------
        if (lane == 0) {
            unsigned emask = 0;
            for (int t = 0; t < T; t++) {
                const int st = t & (STAGES - 1);
                if (t >= STAGES) {
                    mbar_wait(emptyb + 8 * st, (emask >> st) & 1u);
                    emask ^= 1u << st;
                }
                int ts   = r0 + t * TROWS;
                int rows = (r1 - ts < TROWS) ? (r1 - ts) : TROWS;
                uint32_t bytes = (uint32_t)rows * (DIM * 4);
                mbar_expect_tx(fullb + 8 * st, bytes);
                bulk_g2s(sb + st * TILE_BYTES, memory + (size_t)ts * DIM, bytes, fullb + 8 * st);
            }
        }
        __syncthreads();   // join epilogue barrier #1
    } else {
        // -------- consumer warps --------
        ull k2[SLOTS][4];
#pragma unroll
        for (int s = 0; s < SLOTS; s++) {
            ulonglong2 ka = *(const ulonglong2*)(g_k + s * DIM + 4 * lane);
            ulonglong2 kb = *(const ulonglong2*)(g_k + s * DIM + 128 + 4 * lane);
            k2[s][0] = ka.x; k2[s][1] = ka.y; k2[s][2] = kb.x; k2[s][3] = kb.y;
        }
        ull acc2[SLOTS][4];
#pragma unroll
        for (int s = 0; s < SLOTS; s++) {
            acc2[s][0] = 0ull; acc2[s][1] = 0ull; acc2[s][2] = 0ull; acc2[s][3] = 0ull;
        }
        float l_local = 0.f;

        unsigned fmask = 0;
        for (int t = 0; t < T; t++) {
            const int st = t & (STAGES - 1);
            mbar_wait(fullb + 8 * st, (fmask >> st) & 1u);
            fmask ^= 1u << st;

            const int tstart = r0 + t * TROWS;
            const char* tile = smem + st * TILE_BYTES;
#pragma unroll
            for (int i = 0; i < 4; i++) {
                const int rl = warp * 4 + i;
                if (tstart + rl < r1) {
                    const ulonglong2* xp = (const ulonglong2*)(tile + rl * (DIM * 4)) + lane;
                    ulonglong2 A = xp[0];
                    ulonglong2 B = xp[32];
                    process_row(A.x, A.y, B.x, B.y, k2, acc2, l_local, lane);
                }
            }
            __syncwarp();
            if (lane == 0) mbar_arrive(emptyb + 8 * st);
        }

        // ---------------- per-CTA reduction (reuse ring smem) ----------------
        __syncthreads();   // epilogue barrier #1: all consumption done, producer done
        float* sred = (float*)smem;                        // [CWARPS][2048]
        float* sl   = (float*)(smem + CWARPS * 2048 * 4);  // [CWARPS][8]
#pragma unroll
        for (int s = 0; s < SLOTS; s++) {
            float2 u0 = unpack2(acc2[s][0]);
            float2 u1 = unpack2(acc2[s][1]);
            float2 u2 = unpack2(acc2[s][2]);
            float2 u3 = unpack2(acc2[s][3]);
            *(float4*)(sred + warp * 2048 + s * DIM + 4 * lane)       = make_float4(u0.x, u0.y, u1.x, u1.y);
            *(float4*)(sred + warp * 2048 + s * DIM + 128 + 4 * lane) = make_float4(u2.x, u2.y, u3.x, u3.y);
        }
        if ((lane & 3) == 0) sl[warp * 8 + (lane >> 2)] = l_local;
    }

    __syncthreads();       // epilogue barrier #2: sred/sl fully written
    {
        float* sred = (float*)smem;
        float* sl   = (float*)(smem + CWARPS * 2048 * 4);
        for (int e = tid; e < 2048; e += THREADS) {
            float sum = 0.f;
#pragma unroll
            for (int w = 0; w < CWARPS; w++) sum += sred[w * 2048 + e];
            g_pacc[c * 2048 + e] = sum;
        }
        if (tid < 8) {
            float sum = 0.f;
#pragma unroll
            for (int w = 0; w < CWARPS; w++) sum += sl[w * 8 + tid];
            g_pl[c * 8 + tid] = sum;
        }
    }
}

// ===================================================================================
// Kernel 3: reduce per-CTA partials, compute new_heads. 16 x 128 threads
// ===================================================================================
__global__ void k_reduce(const float* __restrict__ heads)
{
    const int e = blockIdx.x * 128 + threadIdx.x;  // 0..2047 (= s*256 + d)
    const int s = e >> 8;
    float acc = 0.f, l = 0.f;
    for (int p = 0; p < NCTA; p++) {
        acc += g_pacc[p * 2048 + e];
        l   += g_pl[p * 8 + s];
    }
    float raw = acc / l;
    float q = g_qspace[e];
    g_newheads[e] = raw * q + (1.f - q) * heads[e];
}

// ===================================================================================
// Kernel 4: new_state = [state; new_heads] @ sW^T + sb. grid 256 x 128 thr, float4
// ===================================================================================
__global__ void k_synth(const float* __restrict__ state, const float* __restrict__ sW,
                        const float* __restrict__ sb)
{
    const int i = blockIdx.x;
    const int t = threadIdx.x;  // 128
    const float4* w4 = (const float4*)(sW + (size_t)i * (DIM * (SLOTS + 1)));
    float p = 0.f;
#pragma unroll
    for (int j4 = t; j4 < (DIM * (SLOTS + 1)) / 4; j4 += 128) {
        float4 w = w4[j4];
        float4 cv;
        if (j4 < DIM / 4) cv = *(const float4*)(state + 4 * j4);
        else              cv = *(const float4*)(g_newheads + 4 * j4 - DIM);
        p += w.x * cv.x + w.y * cv.y + w.z * cv.z + w.w * cv.w;
    }
    __shared__ float sm[128];
    sm[t] = p;
    __syncthreads();
    for (int off = 64; off > 0; off >>= 1) {
        if (t < off) sm[t] += sm[t + off];
        __syncthreads();
    }
    if (t == 0) g_newstate[i] = sm[0] + sb[i];
}

// ===================================================================================
// Kernel 5: reveal = sigmoid(new_state @ rvW^T + rvb); out = new_state * reveal
// ===================================================================================
__global__ void k_out(const float* __restrict__ rvW, const float* __restrict__ rvb,
                      float* __restrict__ out)
{
    const int t = threadIdx.x;  // 256
    float ns = g_newstate[t];
    __shared__ float sm[256];
    sm[t] = ns * rvW[t];
    __syncthreads();
    for (int off = 128; off > 0; off >>= 1) {
        if (t < off) sm[t] += sm[t + off];
        __syncthreads();
    }
    __shared__ float rev;
    if (t == 0) {
        float z = sm[0] + rvb[0];
        rev = 1.f / (1.f + __expf(-z));
    }
    __syncthreads();
    out[t] = ns * rev;
}

// ===================================================================================
extern "C" void kernel_launch(void* const* d_in, const int* in_sizes, int n_in,
                              void* d_out, int out_size)
{
    const float* memory = (const float*)d_in[0];
    const float* heads  = (const float*)d_in[1];
    const float* state  = (const float*)d_in[2];
    const float* qW     = (const float*)d_in[3];
    const float* qb     = (const float*)d_in[4];
    const float* sW     = (const float*)d_in[5];
    const float* sb     = (const float*)d_in[6];
    const float* rvW    = (const float*)d_in[7];
    const float* rvb    = (const float*)d_in[8];
    float* out = (float*)d_out;

    cudaFuncSetAttribute(k_stream, cudaFuncAttributeMaxDynamicSharedMemorySize, DYN_SMEM);

    k_setup<<<DIM, 128>>>(heads, state, qW, qb);
    k_stream<<<NCTA, THREADS, DYN_SMEM>>>(memory);
    k_reduce<<<16, 128>>>(heads);
    k_synth<<<DIM, 128>>>(state, sW, sb);
    k_out<<<1, 256>>>(rvW, rvb, out);
}

// round 4
// speedup vs baseline: 1.3030x; 1.0007x over previous
#include <cuda_runtime.h>
#include <cstdint>

#define DIM     256
#define SLOTS   8
#define NMEM    1000000
#define NCTA    148
#define CWARPS  11                      // consumer warps
#define THREADS 384                     // 11 consumers + 1 producer warp
#define PROD_WARP 11
#define TROWS   44                      // rows per tile (4 per consumer warp)
#define STAGES  4
#define TILE_BYTES  (TROWS * DIM * 4)   // 45056
#define TILES_BYTES (STAGES * TILE_BYTES)
#define DYN_SMEM    (TILES_BYTES + 128)

typedef unsigned long long ull;

// ------------------------- scratch (no allocations allowed) -------------------------
__device__ __align__(256) float g_k[SLOTS * DIM];          // heads*qspace * log2(e)
__device__ __align__(256) float g_qspace[SLOTS * DIM];
__device__ __align__(256) float g_pacc[NCTA * SLOTS * DIM];// per-CTA partial acc
__device__ __align__(256) float g_pl[NCTA * SLOTS];        // per-CTA partial l
__device__ __align__(256) float g_newheads[SLOTS * DIM];
__device__ __align__(256) float g_newstate[DIM];

// ------------------------- helpers -------------------------
__device__ __forceinline__ ull ffma2(ull a, ull b, ull c) {
    ull d; asm("fma.rn.f32x2 %0, %1, %2, %3;" : "=l"(d) : "l"(a), "l"(b), "l"(c)); return d;
}
__device__ __forceinline__ ull fmul2(ull a, ull b) {
    ull d; asm("mul.rn.f32x2 %0, %1, %2;" : "=l"(d) : "l"(a), "l"(b)); return d;
}
__device__ __forceinline__ ull pack2(float lo, float hi) {
    ull r; asm("mov.b64 %0, {%1, %2};" : "=l"(r) : "f"(lo), "f"(hi)); return r;
}
__device__ __forceinline__ float2 unpack2(ull v) {
    float2 f; asm("mov.b64 {%0, %1}, %2;" : "=f"(f.x), "=f"(f.y) : "l"(v)); return f;
}
__device__ __forceinline__ float ex2f(float x) {
    float r; asm("ex2.approx.f32 %0, %1;" : "=f"(r) : "f"(x)); return r;
}
__device__ __forceinline__ uint32_t smem_u32(const void* p) {
    uint32_t a;
    asm("{ .reg .u64 t; cvta.to.shared.u64 t, %1; cvt.u32.u64 %0, t; }" : "=r"(a) : "l"(p));
    return a;
}
__device__ __forceinline__ void mbar_init(uint32_t a, uint32_t cnt) {
    asm volatile("mbarrier.init.shared.b64 [%0], %1;" :: "r"(a), "r"(cnt) : "memory");
}
__device__ __forceinline__ void mbar_expect_tx(uint32_t a, uint32_t bytes) {
    asm volatile("mbarrier.arrive.expect_tx.shared.b64 _, [%0], %1;" :: "r"(a), "r"(bytes) : "memory");
}
__device__ __forceinline__ void mbar_arrive(uint32_t a) {
    asm volatile("mbarrier.arrive.shared.b64 _, [%0];" :: "r"(a) : "memory");
}
__device__ __forceinline__ void mbar_wait(uint32_t a, uint32_t parity) {
    asm volatile(
        "{\n\t.reg .pred P;\n"
        "WL%=:\n\t"
        "mbarrier.try_wait.parity.acquire.cta.shared::cta.b64 P, [%0], %1, 0x989680;\n\t"
        "@P bra.uni WD%=;\n\t"
        "bra.uni WL%=;\n"
        "WD%=:\n\t}"
        :: "r"(a), "r"(parity) : "memory");
}
__device__ __forceinline__ void bulk_g2s(uint32_t dst, const void* src, uint32_t bytes, uint32_t mbar) {
    asm volatile(
        "cp.async.bulk.shared::cta.global.mbarrier::complete_tx::bytes [%0], [%1], %2, [%3];"
        :: "r"(dst), "l"(src), "r"(bytes), "r"(mbar) : "memory");
}

// ===================================================================================
// Kernel 1: qspace = tanh([state; heads_s] @ qW^T + qb); k = heads*qspace*log2(e)
// ===================================================================================
__global__ void k_setup(const float* __restrict__ heads, const float* __restrict__ state,
                        const float* __restrict__ qW, const float* __restrict__ qb)
{
    const int d = blockIdx.x;
    const int t = threadIdx.x;  // 128 threads
    float pc = 0.f;
    float ps[SLOTS];
#pragma unroll
    for (int s = 0; s < SLOTS; s++) ps[s] = 0.f;

    const float* wrow = qW + (size_t)d * (2 * DIM);
    for (int j = t; j < 2 * DIM; j += 128) {
        float w = wrow[j];
        if (j < DIM) {
            pc += w * state[j];
        } else {
            int jj = j - DIM;
#pragma unroll
            for (int s = 0; s < SLOTS; s++) ps[s] += w * heads[s * DIM + jj];
        }
    }

    __shared__ float sm[SLOTS + 1][128];
    sm[SLOTS][t] = pc;
#pragma unroll
    for (int s = 0; s < SLOTS; s++) sm[s][t] = ps[s];
    __syncthreads();
    for (int off = 64; off > 0; off >>= 1) {
        if (t < off) {
#pragma unroll
            for (int s = 0; s <= SLOTS; s++) sm[s][t] += sm[s][t + off];
        }
        __syncthreads();
    }
    if (t < SLOTS) {
        const int s = t;
        float q = tanhf(sm[s][0] + sm[SLOTS][0] + qb[d]);
        g_qspace[s * DIM + d] = q;
        g_k[s * DIM + d] = heads[s * DIM + d] * q * 1.4426950408889634f;
    }
}

// ===================================================================================
// Kernel 2: the 1 GB stream. Warp-specialized: warp 11 = cp.async.bulk producer,
// warps 0-10 = consumers (4 rows each per 44-row tile).
// ===================================================================================
__device__ __forceinline__ void process_row(
    ull x0, ull x1, ull x2, ull x3,
    const ull (&k2)[SLOTS][4], ull (&acc2)[SLOTS][4], float& l_local, int lane)
{
    // scores: 8 fmul2 + 24 ffma2
    float p[SLOTS];
#pragma unroll
    for (int s = 0; s < SLOTS; s++) {
        ull q = fmul2(k2[s][0], x0);
        q = ffma2(k2[s][1], x1, q);
        q = ffma2(k2[s][2], x2, q);
        q = ffma2(k2[s][3], x3, q);
        float2 f = unpack2(q);
        p[s] = f.x + f.y;
    }
    // progressive-split reduction: 16 shfl + 7 sel
#pragma unroll
    for (int s = 0; s < SLOTS; s++) p[s] += __shfl_xor_sync(0xffffffffu, p[s], 16);
    const bool b4 = (lane & 16);
    float a0 = b4 ? p[4] : p[0];
    float a1 = b4 ? p[5] : p[1];
    float a2 = b4 ? p[6] : p[2];
    float a3 = b4 ? p[7] : p[3];
    a0 += __shfl_xor_sync(0xffffffffu, a0, 8);
    a1 += __shfl_xor_sync(0xffffffffu, a1, 8);
    a2 += __shfl_xor_sync(0xffffffffu, a2, 8);
    a3 += __shfl_xor_sync(0xffffffffu, a3, 8);
    const bool b3 = (lane & 8);
    float c0 = b3 ? a2 : a0;
    float c1 = b3 ? a3 : a1;
    c0 += __shfl_xor_sync(0xffffffffu, c0, 4);
    c1 += __shfl_xor_sync(0xffffffffu, c1, 4);
    const bool b2 = (lane & 4);
    float d0 = b2 ? c1 : c0;
    d0 += __shfl_xor_sync(0xffffffffu, d0, 2);
    d0 += __shfl_xor_sync(0xffffffffu, d0, 1);
    // lane 4*s (plus 3 copies) holds score for slot s = 4*bit4+2*bit3+bit2
    float wl = ex2f(d0);
    l_local += ((lane & 3) == 0) ? wl : 0.f;
    float w[SLOTS];
#pragma unroll
    for (int s = 0; s < SLOTS; s++) w[s] = __shfl_sync(0xffffffffu, wl, s * 4);
#pragma unroll
    for (int s = 0; s < SLOTS; s++) {
        ull w2 = pack2(w[s], w[s]);
        acc2[s][0] = ffma2(w2, x0, acc2[s][0]);
        acc2[s][1] = ffma2(w2, x1, acc2[s][1]);
        acc2[s][2] = ffma2(w2, x2, acc2[s][2]);
        acc2[s][3] = ffma2(w2, x3, acc2[s][3]);
    }
}

__global__ void __launch_bounds__(THREADS, 1) k_stream(const float* __restrict__ memory)
{
    extern __shared__ char smem[];
    const int tid  = threadIdx.x;
    const int lane = tid & 31;
    const int warp = tid >> 5;
    const int c = blockIdx.x;
    const int r0 = (int)(((long long)NMEM * c) / NCTA);
    const int r1 = (int)(((long long)NMEM * (c + 1)) / NCTA);
    const int T  = (r1 - r0 + TROWS - 1) / TROWS;

    const uint32_t sb     = smem_u32(smem);
    const uint32_t fullb  = sb + TILES_BYTES;       // full[i]  @ +8*i
    const uint32_t emptyb = fullb + 32;             // empty[i] @ +8*i

    if (tid == 0) {
#pragma unroll
        for (int i = 0; i < STAGES; i++) {
            mbar_init(fullb + 8 * i, 1);
            mbar_init(emptyb + 8 * i, CWARPS);
        }
    }
    __syncthreads();

    if (warp == PROD_WARP) {
        // -------- producer warp: only lane 0 drives the ring --------
        if (lane == 0) {
            unsigned emask = 0;
            for (int t = 0; t < T; t++) {
                const int st = t & (STAGES - 1);
                if (t >= STAGES) {
                    mbar_wait(emptyb + 8 * st, (emask >> st) & 1u);
                    emask ^= 1u << st;
                }
                int ts   = r0 + t * TROWS;
                int rows = (r1 - ts < TROWS) ? (r1 - ts) : TROWS;
                uint32_t bytes = (uint32_t)rows * (DIM * 4);
                mbar_expect_tx(fullb + 8 * st, bytes);
                bulk_g2s(sb + st * TILE_BYTES, memory + (size_t)ts * DIM, bytes, fullb + 8 * st);
            }
        }
        __syncthreads();   // join epilogue barrier #1
    } else {
        // -------- consumer warps --------
        ull k2[SLOTS][4];
#pragma unroll
        for (int s = 0; s < SLOTS; s++) {
            ulonglong2 ka = *(const ulonglong2*)(g_k + s * DIM + 4 * lane);
            ulonglong2 kb = *(const ulonglong2*)(g_k + s * DIM + 128 + 4 * lane);
            k2[s][0] = ka.x; k2[s][1] = ka.y; k2[s][2] = kb.x; k2[s][3] = kb.y;
        }
        ull acc2[SLOTS][4];
#pragma unroll
        for (int s = 0; s < SLOTS; s++) {
            acc2[s][0] = 0ull; acc2[s][1] = 0ull; acc2[s][2] = 0ull; acc2[s][3] = 0ull;
        }
        float l_local = 0.f;

        unsigned fmask = 0;
        for (int t = 0; t < T; t++) {
            const int st = t & (STAGES - 1);
            mbar_wait(fullb + 8 * st, (fmask >> st) & 1u);
            fmask ^= 1u << st;

            const int tstart = r0 + t * TROWS;
            const char* tile = smem + st * TILE_BYTES;
#pragma unroll
            for (int i = 0; i < 4; i++) {
                const int rl = warp * 4 + i;
                if (tstart + rl < r1) {
                    const ulonglong2* xp = (const ulonglong2*)(tile + rl * (DIM * 4)) + lane;
                    ulonglong2 A = xp[0];
                    ulonglong2 B = xp[32];
                    process_row(A.x, A.y, B.x, B.y, k2, acc2, l_local, lane);
                }
            }
            __syncwarp();
            if (lane == 0) mbar_arrive(emptyb + 8 * st);
        }

        // ---------------- per-CTA reduction (reuse ring smem) ----------------
        __syncthreads();   // epilogue barrier #1: all consumption done, producer done
        float* sred = (float*)smem;                        // [CWARPS][2048]
        float* sl   = (float*)(smem + CWARPS * 2048 * 4);  // [CWARPS][8]
#pragma unroll
        for (int s = 0; s < SLOTS; s++) {
            float2 u0 = unpack2(acc2[s][0]);
            float2 u1 = unpack2(acc2[s][1]);
            float2 u2 = unpack2(acc2[s][2]);
            float2 u3 = unpack2(acc2[s][3]);
            *(float4*)(sred + warp * 2048 + s * DIM + 4 * lane)       = make_float4(u0.x, u0.y, u1.x, u1.y);
            *(float4*)(sred + warp * 2048 + s * DIM + 128 + 4 * lane) = make_float4(u2.x, u2.y, u3.x, u3.y);
        }
        if ((lane & 3) == 0) sl[warp * 8 + (lane >> 2)] = l_local;
    }

    __syncthreads();       // epilogue barrier #2: sred/sl fully written
    {
        float* sred = (float*)smem;
        float* sl   = (float*)(smem + CWARPS * 2048 * 4);
        for (int e = tid; e < 2048; e += THREADS) {
            float sum = 0.f;
#pragma unroll
            for (int w = 0; w < CWARPS; w++) sum += sred[w * 2048 + e];
            g_pacc[c * 2048 + e] = sum;
        }
        if (tid < 8) {
            float sum = 0.f;
#pragma unroll
            for (int w = 0; w < CWARPS; w++) sum += sl[w * 8 + tid];
            g_pl[c * 8 + tid] = sum;
        }
    }
}

// ===================================================================================
// Kernel 3: reduce per-CTA partials, compute new_heads. 16 x 128 threads
// ===================================================================================
__global__ void k_reduce(const float* __restrict__ heads)
{
    const int e = blockIdx.x * 128 + threadIdx.x;  // 0..2047 (= s*256 + d)
    const int s = e >> 8;
    float acc = 0.f, l = 0.f;
    for (int p = 0; p < NCTA; p++) {
        acc += g_pacc[p * 2048 + e];
        l   += g_pl[p * 8 + s];
    }
    float raw = acc / l;
    float q = g_qspace[e];
    g_newheads[e] = raw * q + (1.f - q) * heads[e];
}

// ===================================================================================
// Kernel 4: new_state = [state; new_heads] @ sW^T + sb. grid 256 x 128 thr, float4
// ===================================================================================
__global__ void k_synth(const float* __restrict__ state, const float* __restrict__ sW,
                        const float* __restrict__ sb)
{
    const int i = blockIdx.x;
    const int t = threadIdx.x;  // 128
    const float4* w4 = (const float4*)(sW + (size_t)i * (DIM * (SLOTS + 1)));
    float p = 0.f;
#pragma unroll
    for (int j4 = t; j4 < (DIM * (SLOTS + 1)) / 4; j4 += 128) {
        float4 w = w4[j4];
        float4 cv;
        if (j4 < DIM / 4) cv = *(const float4*)(state + 4 * j4);
        else              cv = *(const float4*)(g_newheads + 4 * j4 - DIM);
        p += w.x * cv.x + w.y * cv.y + w.z * cv.z + w.w * cv.w;
    }
    __shared__ float sm[128];
    sm[t] = p;
    __syncthreads();
    for (int off = 64; off > 0; off >>= 1) {
        if (t < off) sm[t] += sm[t + off];
        __syncthreads();
    }
    if (t == 0) g_newstate[i] = sm[0] + sb[i];
}

// ===================================================================================
// Kernel 5: reveal = sigmoid(new_state @ rvW^T + rvb); out = new_state * reveal
// ===================================================================================
__global__ void k_out(const float* __restrict__ rvW, const float* __restrict__ rvb,
                      float* __restrict__ out)
{
    const int t = threadIdx.x;  // 256
    float ns = g_newstate[t];
    __shared__ float sm[256];
    sm[t] = ns * rvW[t];
    __syncthreads();
    for (int off = 128; off > 0; off >>= 1) {
        if (t < off) sm[t] += sm[t + off];
        __syncthreads();
    }
    __shared__ float rev;
    if (t == 0) {
        float z = sm[0] + rvb[0];
        rev = 1.f / (1.f + __expf(-z));
    }
    __syncthreads();
    out[t] = ns * rev;
}

// ===================================================================================
extern "C" void kernel_launch(void* const* d_in, const int* in_sizes, int n_in,
                              void* d_out, int out_size)
{
    const float* memory = (const float*)d_in[0];
    const float* heads  = (const float*)d_in[1];
    const float* state  = (const float*)d_in[2];
    const float* qW     = (const float*)d_in[3];
    const float* qb     = (const float*)d_in[4];
    const float* sW     = (const float*)d_in[5];
    const float* sb     = (const float*)d_in[6];
    const float* rvW    = (const float*)d_in[7];
    const float* rvb    = (const float*)d_in[8];
    float* out = (float*)d_out;

    cudaFuncSetAttribute(k_stream, cudaFuncAttributeMaxDynamicSharedMemorySize, DYN_SMEM);

    k_setup<<<DIM, 128>>>(heads, state, qW, qb);
    k_stream<<<NCTA, THREADS, DYN_SMEM>>>(memory);
    k_reduce<<<16, 128>>>(heads);
    k_synth<<<DIM, 128>>>(state, sW, sb);
    k_out<<<1, 256>>>(rvW, rvb, out);
}

// round 8
// speedup vs baseline: 1.4269x; 1.0951x over previous
#include <cuda_runtime.h>
#include <cstdint>

#define DIM       256
#define SLOTS     8
#define NMEM      1000000
#define NCTA      148
#define THREADS   288                 // 9 warps: 0-7 consumers, 8 producer
#define SROWS     64                  // rows per stage/tile
#define ROWW      260                 // padded row stride in words (1040B)
#define ROWB      1040
#define STG_BYTES (SROWS * ROWB)      // 66560
#define NSTG      3
#define KT_OFF    (NSTG * STG_BYTES)  // 199680 : kT[dim][slot] 8KB
#define WB_OFF    (KT_OFF + 8192)     // 207872 : per-warp w scratch 8 x 1KB
#define LB_OFF    (WB_OFF + 8192)     // 216064 : l partials 256B
#define BARS      (LB_OFF + 256)      // 216320
#define DYN_SMEM  (BARS + 64)         // 216384

typedef unsigned long long ull;

__device__ __align__(256) float g_k[SLOTS * DIM];          // heads*qspace*log2(e)
__device__ __align__(256) float g_qspace[SLOTS * DIM];
__device__ __align__(256) float g_pacc[NCTA * SLOTS * DIM];
__device__ __align__(256) float g_pl[NCTA * SLOTS];
__device__ __align__(256) float g_newheads[SLOTS * DIM];
__device__ __align__(256) float g_newstate[DIM];

__device__ __forceinline__ ull ffma2(ull a, ull b, ull c) {
    ull d; asm("fma.rn.f32x2 %0, %1, %2, %3;" : "=l"(d) : "l"(a), "l"(b), "l"(c)); return d;
}
__device__ __forceinline__ float2 unpack2(ull v) {
    float2 f; asm("mov.b64 {%0, %1}, %2;" : "=f"(f.x), "=f"(f.y) : "l"(v)); return f;
}
__device__ __forceinline__ float ex2f(float x) {
    float r; asm("ex2.approx.f32 %0, %1;" : "=f"(r) : "f"(x)); return r;
}
__device__ __forceinline__ uint32_t smem_u32(const void* p) {
    uint32_t a; asm("{ .reg .u64 t; cvta.to.shared.u64 t, %1; cvt.u32.u64 %0, t; }" : "=r"(a) : "l"(p)); return a;
}
__device__ __forceinline__ void mbar_init(uint32_t a, uint32_t c) {
    asm volatile("mbarrier.init.shared.b64 [%0], %1;" :: "r"(a), "r"(c) : "memory");
}
__device__ __forceinline__ void mbar_arrive(uint32_t a) {
    asm volatile("mbarrier.arrive.release.cta.shared::cta.b64 _, [%0];" :: "r"(a) : "memory");
}
__device__ __forceinline__ void mbar_expect_tx(uint32_t a, uint32_t bytes) {
    asm volatile("mbarrier.arrive.expect_tx.shared.b64 _, [%0], %1;" :: "r"(a), "r"(bytes) : "memory");
}
__device__ __forceinline__ void mbar_wait(uint32_t a, uint32_t par) {
    asm volatile(
        "{\n\t.reg .pred P;\nWL%=:\n\t"
        "mbarrier.try_wait.parity.acquire.cta.shared::cta.b64 P, [%0], %1, 0x989680;\n\t"
        "@P bra.uni WD%=;\n\tbra.uni WL%=;\nWD%=:\n\t}" :: "r"(a), "r"(par) : "memory");
}
__device__ __forceinline__ void fence_async() {
    asm volatile("fence.proxy.async.shared::cta;" ::: "memory");
}
__device__ __forceinline__ void bulk_g2s(uint32_t dst, const void* src, uint32_t bytes, uint32_t mbar) {
    asm volatile("cp.async.bulk.shared::cta.global.mbarrier::complete_tx::bytes [%0], [%1], %2, [%3];"
                 :: "r"(dst), "l"(src), "r"(bytes), "r"(mbar) : "memory");
}
// m16n8k8 tf32 HMMA, raw f32 bits as tf32
__device__ __forceinline__ void mma8(float& d0, float& d1, float& d2, float& d3,
                                     uint32_t a0, uint32_t a1, uint32_t a2, uint32_t a3,
                                     uint32_t b0, uint32_t b1) {
    asm volatile("mma.sync.aligned.m16n8k8.row.col.f32.tf32.tf32.f32 "
                 "{%0,%1,%2,%3}, {%4,%5,%6,%7}, {%8,%9}, {%0,%1,%2,%3};"
                 : "+f"(d0), "+f"(d1), "+f"(d2), "+f"(d3)
                 : "r"(a0), "r"(a1), "r"(a2), "r"(a3), "r"(b0), "r"(b1));
}

// ============================ Kernel 1: setup ============================
__global__ void k_setup(const float* __restrict__ heads, const float* __restrict__ state,
                        const float* __restrict__ qW, const float* __restrict__ qb)
{
    const int d = blockIdx.x, t = threadIdx.x;
    float pc = 0.f, ps[SLOTS];
#pragma unroll
    for (int s = 0; s < SLOTS; s++) ps[s] = 0.f;
    const float* wrow = qW + (size_t)d * (2 * DIM);
    for (int j = t; j < 2 * DIM; j += 128) {
        float w = wrow[j];
        if (j < DIM) pc += w * state[j];
        else {
            int jj = j - DIM;
#pragma unroll
            for (int s = 0; s < SLOTS; s++) ps[s] += w * heads[s * DIM + jj];
        }
    }
    __shared__ float sm[SLOTS + 1][128];
    sm[SLOTS][t] = pc;
#pragma unroll
    for (int s = 0; s < SLOTS; s++) sm[s][t] = ps[s];
    __syncthreads();
    for (int off = 64; off > 0; off >>= 1) {
        if (t < off) {
#pragma unroll
            for (int s = 0; s <= SLOTS; s++) sm[s][t] += sm[s][t + off];
        }
        __syncthreads();
    }
    if (t < SLOTS) {
        float q = tanhf(sm[t][0] + sm[SLOTS][0] + qb[d]);
        g_qspace[t * DIM + d] = q;
        g_k[t * DIM + d] = heads[t * DIM + d] * q * 1.4426950408889634f;
    }
}

// ============================ Kernel 2: stream ============================
__global__ void __launch_bounds__(THREADS, 1) k_stream(const float* __restrict__ memory)
{
    extern __shared__ char smem[];
    const int tid = threadIdx.x, lane = tid & 31, warp = tid >> 5;
    const int c = blockIdx.x;
    const int r0 = (int)(((long long)NMEM * c) / NCTA);
    const int r1 = (int)(((long long)NMEM * (c + 1)) / NCTA);
    const int T  = (r1 - r0 + SROWS - 1) / SROWS;

    const uint32_t sb = smem_u32(smem);
    const uint32_t FULL = sb + BARS, EMPTY = FULL + 24;

    if (tid == 0) {
#pragma unroll
        for (int i = 0; i < NSTG; i++) { mbar_init(FULL + 8 * i, 1); mbar_init(EMPTY + 8 * i, 4); }
    }
    // zero stages (so tail rows hold finite data on first use)
    for (int i = tid; i < (NSTG * STG_BYTES) / 16; i += THREADS)
        *(float4*)(smem + i * 16) = make_float4(0.f, 0.f, 0.f, 0.f);
    // kT[dim][slot]
    {
        float* kT = (float*)(smem + KT_OFF);
        for (int i = tid; i < DIM * SLOTS; i += THREADS) {
            int dimi = i >> 3, s = i & 7;
            kT[dimi * 8 + s] = g_k[s * DIM + dimi];
        }
    }
    fence_async();
    __syncthreads();

    // accumulators (consumers)
    ull acc2[SLOTS][4];
#pragma unroll
    for (int s = 0; s < SLOTS; s++) { acc2[s][0] = acc2[s][1] = acc2[s][2] = acc2[s][3] = 0ull; }
    float lp0 = 0.f, lp1 = 0.f;

    if (warp == 8) {
        // ---------------- producer: per-row cp.async.bulk into padded stage ----------------
        if (lane == 0) {
            for (int t = 0; t < T; t++) {
                const int st = t % 3;
                if (t >= 3) mbar_wait(EMPTY + 8 * st, (t / 3 - 1) & 1);
                const int ts = r0 + t * SROWS;
                const int rows = (r1 - ts < SROWS) ? (r1 - ts) : SROWS;
                mbar_expect_tx(FULL + 8 * st, (uint32_t)rows * 1024u);
                const float* src = memory + (size_t)ts * DIM;
                uint32_t dst = sb + st * STG_BYTES;
#pragma unroll 4
                for (int r = 0; r < rows; r++)
                    bulk_g2s(dst + r * ROWB, src + (size_t)r * DIM, 1024u, FULL + 8 * st);
            }
        }
    } else {
        // ---------------- consumers: warps 0-3 even tiles, 4-7 odd tiles ----------------
        const int g = warp >> 2, wgl = warp & 3;
        const int rowbase = wgl * 16;
        const uint32_t* kTu = (const uint32_t*)(smem + KT_OFF);
        const uint32_t* bb = kTu + (lane & 3) * 8 + (lane >> 2);
        float* wb = (float*)(smem + WB_OFF + warp * 1024);

        for (int t = g; t < T; t += 2) {
            const int st = t % 3;
            mbar_wait(FULL + 8 * st, (t / 3) & 1);
            const int tstart = r0 + t * SROWS;
            const char* tile = smem + st * STG_BYTES;

            // ---- scores via tf32 HMMA: D[16 rows x 8 slots] ----
            float d0 = 0.f, d1 = 0.f, d2 = 0.f, d3 = 0.f;
            const uint32_t* af = (const uint32_t*)tile + (rowbase + (lane >> 2)) * ROWW + (lane & 3);
#pragma unroll 8
            for (int ks = 0; ks < 32; ks++) {
                uint32_t a0 = af[ks * 8];
                uint32_t a1 = af[ks * 8 + 8 * ROWW];
                uint32_t a2 = af[ks * 8 + 4];
                uint32_t a3 = af[ks * 8 + 8 * ROWW + 4];
                uint32_t b0 = bb[ks * 64];
                uint32_t b1 = bb[ks * 64 + 32];
                mma8(d0, d1, d2, d3, a0, a1, a2, a3, b0, b1);
            }
            // ---- exp + mask + stash dup pairs ----
            const int row0 = tstart + rowbase + (lane >> 2);
            const int row1 = row0 + 8;
            float w0 = (row0 < r1) ? ex2f(d0) : 0.f;
            float w1 = (row0 < r1) ? ex2f(d1) : 0.f;
            float w2 = (row1 < r1) ? ex2f(d2) : 0.f;
            float w3 = (row1 < r1) ? ex2f(d3) : 0.f;
            lp0 += w0 + w2;
            lp1 += w1 + w3;
            *(float4*)(wb + (lane >> 2) * 16 + (lane & 3) * 4)       = make_float4(w0, w0, w1, w1);
            *(float4*)(wb + (lane >> 2) * 16 + 128 + (lane & 3) * 4) = make_float4(w2, w2, w3, w3);
            __syncwarp();

            // ---- accumulate: acc2[s] += w[row][s] * x[row][dims of lane] ----
#pragma unroll 2
            for (int r = 0; r < 16; r++) {
                const char* xrow = tile + (rowbase + r) * ROWB;
                ull x01 = ((const ull*)xrow)[2 * lane];
                ull x23 = ((const ull*)xrow)[2 * lane + 1];
                ull x45 = ((const ull*)(xrow + 512))[2 * lane];
                ull x67 = ((const ull*)(xrow + 512))[2 * lane + 1];
                const float4* wd4 = (const float4*)(wb + r * 16);
#pragma unroll
                for (int j = 0; j < 4; j++) {
                    float4 wp = wd4[j];
                    ull wa, wbp;
                    asm("mov.b64 %0, {%2, %3}; mov.b64 %1, {%4, %5};"
                        : "=l"(wa), "=l"(wbp) : "f"(wp.x), "f"(wp.y), "f"(wp.z), "f"(wp.w));
                    acc2[2 * j][0]     = ffma2(wa, x01, acc2[2 * j][0]);
                    acc2[2 * j][1]     = ffma2(wa, x23, acc2[2 * j][1]);
                    acc2[2 * j][2]     = ffma2(wa, x45, acc2[2 * j][2]);
                    acc2[2 * j][3]     = ffma2(wa, x67, acc2[2 * j][3]);
                    acc2[2 * j + 1][0] = ffma2(wbp, x01, acc2[2 * j + 1][0]);
                    acc2[2 * j + 1][1] = ffma2(wbp, x23, acc2[2 * j + 1][1]);
                    acc2[2 * j + 1][2] = ffma2(wbp, x45, acc2[2 * j + 1][2]);
                    acc2[2 * j + 1][3] = ffma2(wbp, x67, acc2[2 * j + 1][3]);
                }
            }
            __syncwarp();
            if (lane == 0) mbar_arrive(EMPTY + 8 * st);
        }
    }

    __syncthreads();   // pipeline fully drained — smem reusable
    if (warp < 8) {
        // lane owns dims {4*lane..4*lane+3} and {128+4*lane..+3}
        float* dst = (float*)(smem + warp * 8192);
#pragma unroll
        for (int s = 0; s < SLOTS; s++) {
            float2 u0 = unpack2(acc2[s][0]);
            float2 u1 = unpack2(acc2[s][1]);
            float2 u2 = unpack2(acc2[s][2]);
            float2 u3 = unpack2(acc2[s][3]);
            *(float4*)(dst + s * DIM + 4 * lane)       = make_float4(u0.x, u0.y, u1.x, u1.y);
            *(float4*)(dst + s * DIM + 128 + 4 * lane) = make_float4(u2.x, u2.y, u3.x, u3.y);
        }
        // reduce l partials across lane>>2 groups
#pragma unroll
        for (int m = 4; m < 32; m <<= 1) {
            lp0 += __shfl_xor_sync(0xffffffffu, lp0, m);
            lp1 += __shfl_xor_sync(0xffffffffu, lp1, m);
        }
        if (lane < 4) {
            float* lb = (float*)(smem + LB_OFF);
            lb[warp * 8 + 2 * lane]     = lp0;
            lb[warp * 8 + 2 * lane + 1] = lp1;
        }
    }
    __syncthreads();
    for (int e = tid; e < 2048; e += THREADS) {
        float sum = 0.f;
#pragma unroll
        for (int w = 0; w < 8; w++) sum += ((const float*)(smem + w * 8192))[e];
        g_pacc[c * 2048 + e] = sum;
    }
    if (tid < 8) {
        const float* lb = (const float*)(smem + LB_OFF);
        float sum = 0.f;
#pragma unroll
        for (int w = 0; w < 8; w++) sum += lb[w * 8 + tid];
        g_pl[c * 8 + tid] = sum;
    }
}

// ============================ Kernel 3: reduce ============================
__global__ void k_reduce(const float* __restrict__ heads)
{
    const int e = blockIdx.x * 128 + threadIdx.x;
    const int s = e >> 8;
    float acc = 0.f, l = 0.f;
    for (int p = 0; p < NCTA; p++) { acc += g_pacc[p * 2048 + e]; l += g_pl[p * 8 + s]; }
    float raw = acc / l;
    float q = g_qspace[e];
    g_newheads[e] = raw * q + (1.f - q) * heads[e];
}

// ============================ Kernel 4: synth ============================
__global__ void k_synth(const float* __restrict__ state, const float* __restrict__ sW,
                        const float* __restrict__ sb)
{
    const int i = blockIdx.x, t = threadIdx.x;
    const float4* w4 = (const float4*)(sW + (size_t)i * (DIM * (SLOTS + 1)));
    float p = 0.f;
#pragma unroll
    for (int j4 = t; j4 < (DIM * (SLOTS + 1)) / 4; j4 += 128) {
        float4 w = w4[j4];
        float4 cv = (j4 < DIM / 4) ? *(const float4*)(state + 4 * j4)
                                   : *(const float4*)(g_newheads + 4 * j4 - DIM);
        p += w.x * cv.x + w.y * cv.y + w.z * cv.z + w.w * cv.w;
    }
    __shared__ float sm[128];
    sm[t] = p;
    __syncthreads();
    for (int off = 64; off > 0; off >>= 1) { if (t < off) sm[t] += sm[t + off]; __syncthreads(); }
    if (t == 0) g_newstate[i] = sm[0] + sb[i];
}

// ============================ Kernel 5: out ============================
__global__ void k_out(const float* __restrict__ rvW, const float* __restrict__ rvb,
                      float* __restrict__ out)
{
    const int t = threadIdx.x;
    float ns = g_newstate[t];
    __shared__ float sm[256];
    sm[t] = ns * rvW[t];
    __syncthreads();
    for (int off = 128; off > 0; off >>= 1) { if (t < off) sm[t] += sm[t + off]; __syncthreads(); }
    __shared__ float rev;
    if (t == 0) rev = 1.f / (1.f + __expf(-(sm[0] + rvb[0])));
    __syncthreads();
    out[t] = ns * rev;
}

// ===================================================================================
extern "C" void kernel_launch(void* const* d_in, const int* in_sizes, int n_in,
                              void* d_out, int out_size)
{
    const float* memory = (const float*)d_in[0];
    const float* heads  = (const float*)d_in[1];
    const float* state  = (const float*)d_in[2];
    const float* qW     = (const float*)d_in[3];
    const float* qb     = (const float*)d_in[4];
    const float* sW     = (const float*)d_in[5];
    const float* sb     = (const float*)d_in[6];
    const float* rvW    = (const float*)d_in[7];
    const float* rvb    = (const float*)d_in[8];
    float* out = (float*)d_out;

    cudaFuncSetAttribute(k_stream, cudaFuncAttributeMaxDynamicSharedMemorySize, DYN_SMEM);

    k_setup<<<DIM, 128>>>(heads, state, qW, qb);
    k_stream<<<NCTA, THREADS, DYN_SMEM>>>(memory);
    k_reduce<<<16, 128>>>(heads);
    k_synth<<<DIM, 128>>>(state, sW, sb);
    k_out<<<1, 256>>>(rvW, rvb, out);
}

// round 10
// speedup vs baseline: 1.9011x; 1.3323x over previous
#include <cuda_runtime.h>
#include <cstdint>

#define DIM       256
#define SLOTS     8
#define NMEM      1000000
#define NCTA      148
#define THREADS   288                 // 9 warps: 0-7 consumers, 8 producer
#define SROWS     64                  // rows per stage/tile (32 pairs)
#define PAIRB     2080                // 2 rows (2048B) + 32B pad
#define STG_BYTES (32 * PAIRB)        // 66560
#define NSTG      3
#define KT_OFF    (NSTG * STG_BYTES)  // 199680 : kT[dim][slot] 8KB
#define WB_OFF    (KT_OFF + 8192)     // 207872 : per-warp w scratch 8 x 1KB
#define LB_OFF    (WB_OFF + 8192)     // 216064 : l partials 256B
#define BARS      (LB_OFF + 256)      // 216320
#define DYN_SMEM  (BARS + 64)         // 216384

typedef unsigned long long ull;

__device__ __align__(256) float g_k[SLOTS * DIM];          // heads*qspace*log2(e)
__device__ __align__(256) float g_qspace[SLOTS * DIM];
__device__ __align__(256) float g_pacc[NCTA * SLOTS * DIM];
__device__ __align__(256) float g_pl[NCTA * SLOTS];
__device__ __align__(256) float g_newheads[SLOTS * DIM];
__device__ __align__(256) float g_newstate[DIM];

__device__ __forceinline__ ull ffma2(ull a, ull b, ull c) {
    ull d; asm("fma.rn.f32x2 %0, %1, %2, %3;" : "=l"(d) : "l"(a), "l"(b), "l"(c)); return d;
}
__device__ __forceinline__ float2 unpack2(ull v) {
    float2 f; asm("mov.b64 {%0, %1}, %2;" : "=f"(f.x), "=f"(f.y) : "l"(v)); return f;
}
__device__ __forceinline__ float ex2f(float x) {
    float r; asm("ex2.approx.f32 %0, %1;" : "=f"(r) : "f"(x)); return r;
}
__device__ __forceinline__ uint32_t smem_u32(const void* p) {
    uint32_t a; asm("{ .reg .u64 t; cvta.to.shared.u64 t, %1; cvt.u32.u64 %0, t; }" : "=r"(a) : "l"(p)); return a;
}
__device__ __forceinline__ void mbar_init(uint32_t a, uint32_t c) {
    asm volatile("mbarrier.init.shared.b64 [%0], %1;" :: "r"(a), "r"(c) : "memory");
}
__device__ __forceinline__ void mbar_arrive(uint32_t a) {
    asm volatile("mbarrier.arrive.release.cta.shared::cta.b64 _, [%0];" :: "r"(a) : "memory");
}
__device__ __forceinline__ void mbar_expect_tx(uint32_t a, uint32_t bytes) {
    asm volatile("mbarrier.arrive.expect_tx.shared.b64 _, [%0], %1;" :: "r"(a), "r"(bytes) : "memory");
}
__device__ __forceinline__ void mbar_wait(uint32_t a, uint32_t par) {
    asm volatile(
        "{\n\t.reg .pred P;\nWL%=:\n\t"
        "mbarrier.try_wait.parity.acquire.cta.shared::cta.b64 P, [%0], %1, 0x989680;\n\t"
        "@P bra.uni WD%=;\n\tbra.uni WL%=;\nWD%=:\n\t}" :: "r"(a), "r"(par) : "memory");
}
__device__ __forceinline__ void bulk_g2s(uint32_t dst, const void* src, uint32_t bytes, uint32_t mbar) {
    asm volatile("cp.async.bulk.shared::cta.global.mbarrier::complete_tx::bytes [%0], [%1], %2, [%3];"
                 :: "r"(dst), "l"(src), "r"(bytes), "r"(mbar) : "memory");
}
// m16n8k8 tf32 HMMA, raw f32 bits as tf32
__device__ __forceinline__ void mma8(float& d0, float& d1, float& d2, float& d3,
                                     uint32_t a0, uint32_t a1, uint32_t a2, uint32_t a3,
                                     uint32_t b0, uint32_t b1) {
    asm volatile("mma.sync.aligned.m16n8k8.row.col.f32.tf32.tf32.f32 "
                 "{%0,%1,%2,%3}, {%4,%5,%6,%7}, {%8,%9}, {%0,%1,%2,%3};"
                 : "+f"(d0), "+f"(d1), "+f"(d2), "+f"(d3)
                 : "r"(a0), "r"(a1), "r"(a2), "r"(a3), "r"(b0), "r"(b1));
}

// ============================ Kernel 1: setup ============================
__global__ void k_setup(const float* __restrict__ heads, const float* __restrict__ state,
                        const float* __restrict__ qW, const float* __restrict__ qb)
{
    const int d = blockIdx.x, t = threadIdx.x;
    float pc = 0.f, ps[SLOTS];
#pragma unroll
    for (int s = 0; s < SLOTS; s++) ps[s] = 0.f;
    const float* wrow = qW + (size_t)d * (2 * DIM);
    for (int j = t; j < 2 * DIM; j += 128) {
        float w = wrow[j];
        if (j < DIM) pc += w * state[j];
        else {
            int jj = j - DIM;
#pragma unroll
            for (int s = 0; s < SLOTS; s++) ps[s] += w * heads[s * DIM + jj];
        }
    }
    __shared__ float sm[SLOTS + 1][128];
    sm[SLOTS][t] = pc;
#pragma unroll
    for (int s = 0; s < SLOTS; s++) sm[s][t] = ps[s];
    __syncthreads();
    for (int off = 64; off > 0; off >>= 1) {
        if (t < off) {
#pragma unroll
            for (int s = 0; s <= SLOTS; s++) sm[s][t] += sm[s][t + off];
        }
        __syncthreads();
    }
    if (t < SLOTS) {
        float q = tanhf(sm[t][0] + sm[SLOTS][0] + qb[d]);
        g_qspace[t * DIM + d] = q;
        g_k[t * DIM + d] = heads[t * DIM + d] * q * 1.4426950408889634f;
    }
}

// ============================ Kernel 2: stream ============================
__global__ void __launch_bounds__(THREADS, 1) k_stream(const float* __restrict__ memory)
{
    extern __shared__ char smem[];
    const int tid = threadIdx.x, lane = tid & 31, warp = tid >> 5;
    const int c = blockIdx.x;
    const int r0 = (int)(((long long)NMEM * c) / NCTA);
    const int r1 = (int)(((long long)NMEM * (c + 1)) / NCTA);
    const int T  = (r1 - r0 + SROWS - 1) / SROWS;

    const uint32_t sb = smem_u32(smem);
    const uint32_t FULL = sb + BARS, EMPTY = FULL + 24;

    if (tid == 0) {
#pragma unroll
        for (int i = 0; i < NSTG; i++) { mbar_init(FULL + 8 * i, 1); mbar_init(EMPTY + 8 * i, 4); }
    }
    // zero stages (tail rows finite on first use; later reuse masked via w=0)
    for (int i = tid; i < (NSTG * STG_BYTES) / 16; i += THREADS)
        *(float4*)(smem + i * 16) = make_float4(0.f, 0.f, 0.f, 0.f);
    // kT[dim][slot]
    {
        float* kT = (float*)(smem + KT_OFF);
        for (int i = tid; i < DIM * SLOTS; i += THREADS) {
            int dimi = i >> 3, s = i & 7;
            kT[dimi * 8 + s] = g_k[s * DIM + dimi];
        }
    }
    __syncthreads();

    // accumulators (consumers)
    ull acc2[SLOTS][4];
#pragma unroll
    for (int s = 0; s < SLOTS; s++) { acc2[s][0] = acc2[s][1] = acc2[s][2] = acc2[s][3] = 0ull; }
    float lp0 = 0.f, lp1 = 0.f;

    if (warp == 8) {
        // ------- producer: 32 x 2-row (2048B) bulk commands per tile, one per lane -------
        for (int t = 0; t < T; t++) {
            const int st = t % 3;
            if (t >= 3) mbar_wait(EMPTY + 8 * st, (t / 3 - 1) & 1);
            const int ts = r0 + t * SROWS;
            const int rows = (r1 - ts < SROWS) ? (r1 - ts) : SROWS;
            if (lane == 0) mbar_expect_tx(FULL + 8 * st, (uint32_t)rows * 1024u);
            __syncwarp();
            const int row0 = 2 * lane;
            if (row0 < rows) {
                const uint32_t bytes = (rows - row0 >= 2) ? 2048u : 1024u;
                bulk_g2s(sb + st * STG_BYTES + lane * PAIRB,
                         memory + (size_t)(ts + row0) * DIM, bytes, FULL + 8 * st);
            }
        }
    } else {
        // ---------------- consumers: warps 0-3 even tiles, 4-7 odd tiles ----------------
        const int g = warp >> 2, wgl = warp & 3;
        const int rowbase = wgl * 16;
        const uint32_t* kTu = (const uint32_t*)(smem + KT_OFF);
        const uint32_t* bb = kTu + (lane & 3) * 8 + (lane >> 2);
        float* wb = (float*)(smem + WB_OFF + warp * 1024);

        // per-lane A-fragment base: row rowA = rowbase + (lane>>2); row+8 = +8320B (4 pairs)
        const int rowA = rowbase + (lane >> 2);
        const uint32_t aoff = (uint32_t)((rowA >> 1) * PAIRB + (rowA & 1) * 1024);

        for (int t = g; t < T; t += 2) {
            const int st = t % 3;
            mbar_wait(FULL + 8 * st, (t / 3) & 1);
            const int tstart = r0 + t * SROWS;
            const char* tile = smem + st * STG_BYTES;

            // ---- scores via tf32 HMMA: D[16 rows x 8 slots] ----
            float d0 = 0.f, d1 = 0.f, d2 = 0.f, d3 = 0.f;
            const uint32_t* af = (const uint32_t*)(tile + aoff) + (lane & 3);
#pragma unroll 8
            for (int ks = 0; ks < 32; ks++) {
                uint32_t a0 = af[ks * 8];
                uint32_t a1 = af[ks * 8 + 2080];      // +8320B = 4 pairs
                uint32_t a2 = af[ks * 8 + 4];
                uint32_t a3 = af[ks * 8 + 2084];
                uint32_t b0 = bb[ks * 64];
                uint32_t b1 = bb[ks * 64 + 32];
                mma8(d0, d1, d2, d3, a0, a1, a2, a3, b0, b1);
            }
            // ---- exp + mask + stash dup pairs ----
            const int row0 = tstart + rowbase + (lane >> 2);
            const int row1 = row0 + 8;
            float w0 = (row0 < r1) ? ex2f(d0) : 0.f;
            float w1 = (row0 < r1) ? ex2f(d1) : 0.f;
            float w2 = (row1 < r1) ? ex2f(d2) : 0.f;
            float w3 = (row1 < r1) ? ex2f(d3) : 0.f;
            lp0 += w0 + w2;
            lp1 += w1 + w3;
            *(float4*)(wb + (lane >> 2) * 16 + (lane & 3) * 4)       = make_float4(w0, w0, w1, w1);
            *(float4*)(wb + (lane >> 2) * 16 + 128 + (lane & 3) * 4) = make_float4(w2, w2, w3, w3);
            __syncwarp();

            // ---- accumulate: acc2[s] += w[row][s] * x[row][dims of lane] ----
#pragma unroll 2
            for (int r = 0; r < 16; r++) {
                const int rr = rowbase + r;
                const char* xrow = tile + (rr >> 1) * PAIRB + (rr & 1) * 1024;
                ull x01 = ((const ull*)xrow)[2 * lane];
                ull x23 = ((const ull*)xrow)[2 * lane + 1];
                ull x45 = ((const ull*)(xrow + 512))[2 * lane];
                ull x67 = ((const ull*)(xrow + 512))[2 * lane + 1];
                const float4* wd4 = (const float4*)(wb + r * 16);
#pragma unroll
                for (int j = 0; j < 4; j++) {
                    float4 wp = wd4[j];
                    ull wa, wbp;
                    asm("mov.b64 %0, {%2, %3}; mov.b64 %1, {%4, %5};"
                        : "=l"(wa), "=l"(wbp) : "f"(wp.x), "f"(wp.y), "f"(wp.z), "f"(wp.w));
                    acc2[2 * j][0]     = ffma2(wa, x01, acc2[2 * j][0]);
                    acc2[2 * j][1]     = ffma2(wa, x23, acc2[2 * j][1]);
                    acc2[2 * j][2]     = ffma2(wa, x45, acc2[2 * j][2]);
                    acc2[2 * j][3]     = ffma2(wa, x67, acc2[2 * j][3]);
                    acc2[2 * j + 1][0] = ffma2(wbp, x01, acc2[2 * j + 1][0]);
                    acc2[2 * j + 1][1] = ffma2(wbp, x23, acc2[2 * j + 1][1]);
                    acc2[2 * j + 1][2] = ffma2(wbp, x45, acc2[2 * j + 1][2]);
                    acc2[2 * j + 1][3] = ffma2(wbp, x67, acc2[2 * j + 1][3]);
                }
            }
            __syncwarp();
            if (lane == 0) mbar_arrive(EMPTY + 8 * st);
        }
    }

    __syncthreads();   // pipeline fully drained — smem reusable
    if (warp < 8) {
        float* dst = (float*)(smem + warp * 8192);
#pragma unroll
        for (int s = 0; s < SLOTS; s++) {
            float2 u0 = unpack2(acc2[s][0]);
            float2 u1 = unpack2(acc2[s][1]);
            float2 u2 = unpack2(acc2[s][2]);
            float2 u3 = unpack2(acc2[s][3]);
            *(float4*)(dst + s * DIM + 4 * lane)       = make_float4(u0.x, u0.y, u1.x, u1.y);
            *(float4*)(dst + s * DIM + 128 + 4 * lane) = make_float4(u2.x, u2.y, u3.x, u3.y);
        }
#pragma unroll
        for (int m = 4; m < 32; m <<= 1) {
            lp0 += __shfl_xor_sync(0xffffffffu, lp0, m);
            lp1 += __shfl_xor_sync(0xffffffffu, lp1, m);
        }
        if (lane < 4) {
            float* lb = (float*)(smem + LB_OFF);
            lb[warp * 8 + 2 * lane]     = lp0;
            lb[warp * 8 + 2 * lane + 1] = lp1;
        }
    }
    __syncthreads();
    for (int e = tid; e < 2048; e += THREADS) {
        float sum = 0.f;
#pragma unroll
        for (int w = 0; w < 8; w++) sum += ((const float*)(smem + w * 8192))[e];
        g_pacc[c * 2048 + e] = sum;
    }
    if (tid < 8) {
        const float* lb = (const float*)(smem + LB_OFF);
        float sum = 0.f;
#pragma unroll
        for (int w = 0; w < 8; w++) sum += lb[w * 8 + tid];
        g_pl[c * 8 + tid] = sum;
    }
}

// ============================ Kernel 3: reduce ============================
__global__ void k_reduce(const float* __restrict__ heads)
{
    const int e = blockIdx.x * 128 + threadIdx.x;
    const int s = e >> 8;
    float acc = 0.f, l = 0.f;
    for (int p = 0; p < NCTA; p++) { acc += g_pacc[p * 2048 + e]; l += g_pl[p * 8 + s]; }
    float raw = acc / l;
    float q = g_qspace[e];
    g_newheads[e] = raw * q + (1.f - q) * heads[e];
}

// ============================ Kernel 4: synth ============================
__global__ void k_synth(const float* __restrict__ state, const float* __restrict__ sW,
                        const float* __restrict__ sb)
{
    const int i = blockIdx.x, t = threadIdx.x;
    const float4* w4 = (const float4*)(sW + (size_t)i * (DIM * (SLOTS + 1)));
    float p = 0.f;
#pragma unroll
    for (int j4 = t; j4 < (DIM * (SLOTS + 1)) / 4; j4 += 128) {
        float4 w = w4[j4];
        float4 cv = (j4 < DIM / 4) ? *(const float4*)(state + 4 * j4)
                                   : *(const float4*)(g_newheads + 4 * j4 - DIM);
        p += w.x * cv.x + w.y * cv.y + w.z * cv.z + w.w * cv.w;
    }
    __shared__ float sm[128];
    sm[t] = p;
    __syncthreads();
    for (int off = 64; off > 0; off >>= 1) { if (t < off) sm[t] += sm[t + off]; __syncthreads(); }
    if (t == 0) g_newstate[i] = sm[0] + sb[i];
}

// ============================ Kernel 5: out ============================
__global__ void k_out(const float* __restrict__ rvW, const float* __restrict__ rvb,
                      float* __restrict__ out)
{
    const int t = threadIdx.x;
    float ns = g_newstate[t];
    __shared__ float sm[256];
    sm[t] = ns * rvW[t];
    __syncthreads();
    for (int off = 128; off > 0; off >>= 1) { if (t < off) sm[t] += sm[t + off]; __syncthreads(); }
    __shared__ float rev;
    if (t == 0) rev = 1.f / (1.f + __expf(-(sm[0] + rvb[0])));
    __syncthreads();
    out[t] = ns * rev;
}

// ===================================================================================
extern "C" void kernel_launch(void* const* d_in, const int* in_sizes, int n_in,
                              void* d_out, int out_size)
{
    const float* memory = (const float*)d_in[0];
    const float* heads  = (const float*)d_in[1];
    const float* state  = (const float*)d_in[2];
    const float* qW     = (const float*)d_in[3];
    const float* qb     = (const float*)d_in[4];
    const float* sW     = (const float*)d_in[5];
    const float* sb     = (const float*)d_in[6];
    const float* rvW    = (const float*)d_in[7];
    const float* rvb    = (const float*)d_in[8];
    float* out = (float*)d_out;

    cudaFuncSetAttribute(k_stream, cudaFuncAttributeMaxDynamicSharedMemorySize, DYN_SMEM);

    k_setup<<<DIM, 128>>>(heads, state, qW, qb);
    k_stream<<<NCTA, THREADS, DYN_SMEM>>>(memory);
    k_reduce<<<16, 128>>>(heads);
    k_synth<<<DIM, 128>>>(state, sW, sb);
    k_out<<<1, 256>>>(rvW, rvb, out);
}

// round 12
// speedup vs baseline: 1.9214x; 1.0107x over previous
#include <cuda_runtime.h>
#include <cstdint>

#define DIM       256
#define SLOTS     8
#define NMEM      1000000
#define NCTA      148
#define THREADS   288                 // 9 warps: 0-7 consumers, 8 producer
#define SROWS     64                  // rows per stage/tile (32 pairs)
#define PAIRB     2080                // 2 rows (2048B) + 32B pad
#define STG_BYTES (32 * PAIRB)        // 66560
#define NSTG      3
#define KT_OFF    (NSTG * STG_BYTES)  // 199680 : kT[dim][slot] 8KB
#define WB_OFF    (KT_OFF + 8192)     // 207872 : per-warp w scratch 8 x 1KB
#define LB_OFF    (WB_OFF + 8192)     // 216064 : l partials 256B
#define BARS      (LB_OFF + 256)      // 216320
#define DYN_SMEM  (BARS + 64)         // 216384

typedef unsigned long long ull;

__device__ __align__(256) float g_k[SLOTS * DIM];          // heads*qspace*log2(e)
__device__ __align__(256) float g_qspace[SLOTS * DIM];
__device__ __align__(256) float g_pacc[NCTA * SLOTS * DIM];
__device__ __align__(256) float g_pl[NCTA * SLOTS];
__device__ __align__(256) float g_newheads[SLOTS * DIM];
__device__ __align__(256) float g_newstate[DIM];

__device__ __forceinline__ ull ffma2(ull a, ull b, ull c) {
    ull d; asm("fma.rn.f32x2 %0, %1, %2, %3;" : "=l"(d) : "l"(a), "l"(b), "l"(c)); return d;
}
__device__ __forceinline__ float2 unpack2(ull v) {
    float2 f; asm("mov.b64 {%0, %1}, %2;" : "=f"(f.x), "=f"(f.y) : "l"(v)); return f;
}
__device__ __forceinline__ float ex2f(float x) {
    float r; asm("ex2.approx.f32 %0, %1;" : "=f"(r) : "f"(x)); return r;
}
__device__ __forceinline__ uint32_t smem_u32(const void* p) {
    uint32_t a; asm("{ .reg .u64 t; cvta.to.shared.u64 t, %1; cvt.u32.u64 %0, t; }" : "=r"(a) : "l"(p)); return a;
}
__device__ __forceinline__ void mbar_init(uint32_t a, uint32_t c) {
    asm volatile("mbarrier.init.shared.b64 [%0], %1;" :: "r"(a), "r"(c) : "memory");
}
__device__ __forceinline__ void mbar_arrive(uint32_t a) {
    asm volatile("mbarrier.arrive.release.cta.shared::cta.b64 _, [%0];" :: "r"(a) : "memory");
}
__device__ __forceinline__ void mbar_expect_tx(uint32_t a, uint32_t bytes) {
    asm volatile("mbarrier.arrive.expect_tx.shared.b64 _, [%0], %1;" :: "r"(a), "r"(bytes) : "memory");
}
__device__ __forceinline__ void mbar_wait(uint32_t a, uint32_t par) {
    asm volatile(
        "{\n\t.reg .pred P;\nWL%=:\n\t"
        "mbarrier.try_wait.parity.acquire.cta.shared::cta.b64 P, [%0], %1, 0x989680;\n\t"
        "@P bra.uni WD%=;\n\tbra.uni WL%=;\nWD%=:\n\t}" :: "r"(a), "r"(par) : "memory");
}
__device__ __forceinline__ void bulk_g2s(uint32_t dst, const void* src, uint32_t bytes, uint32_t mbar) {
    asm volatile("cp.async.bulk.shared::cta.global.mbarrier::complete_tx::bytes [%0], [%1], %2, [%3];"
                 :: "r"(dst), "l"(src), "r"(bytes), "r"(mbar) : "memory");
}
// m16n8k8 tf32 HMMA, raw f32 bits as tf32
__device__ __forceinline__ void mma8(float& d0, float& d1, float& d2, float& d3,
                                     uint32_t a0, uint32_t a1, uint32_t a2, uint32_t a3,
                                     uint32_t b0, uint32_t b1) {
    asm volatile("mma.sync.aligned.m16n8k8.row.col.f32.tf32.tf32.f32 "
                 "{%0,%1,%2,%3}, {%4,%5,%6,%7}, {%8,%9}, {%0,%1,%2,%3};"
                 : "+f"(d0), "+f"(d1), "+f"(d2), "+f"(d3)
                 : "r"(a0), "r"(a1), "r"(a2), "r"(a3), "r"(b0), "r"(b1));
}

// ============================ Kernel 1: setup (warp-per-d) ============================
__global__ void __launch_bounds__(1024) k_setup(const float* __restrict__ heads,
                                                const float* __restrict__ state,
                                                const float* __restrict__ qW,
                                                const float* __restrict__ qb)
{
    const int d = (blockIdx.x * 1024 + threadIdx.x) >> 5;   // 0..255
    const int lane = threadIdx.x & 31;
    float pc = 0.f, ps[SLOTS];
#pragma unroll
    for (int s = 0; s < SLOTS; s++) ps[s] = 0.f;
    const float* wrow = qW + (size_t)d * (2 * DIM);
#pragma unroll
    for (int it = 0; it < 8; it++) {
        int j = lane + it * 32;
        pc += wrow[j] * state[j];
    }
#pragma unroll
    for (int it = 0; it < 8; it++) {
        int jj = lane + it * 32;
        float w = wrow[DIM + jj];
#pragma unroll
        for (int s = 0; s < SLOTS; s++) ps[s] += w * heads[s * DIM + jj];
    }
#pragma unroll
    for (int m = 16; m >= 1; m >>= 1) {
        pc += __shfl_xor_sync(0xffffffffu, pc, m);
#pragma unroll
        for (int s = 0; s < SLOTS; s++) ps[s] += __shfl_xor_sync(0xffffffffu, ps[s], m);
    }
    if (lane == 0) {
        float b = qb[d];
#pragma unroll
        for (int s = 0; s < SLOTS; s++) {
            float q = tanhf(ps[s] + pc + b);
            g_qspace[s * DIM + d] = q;
            g_k[s * DIM + d] = heads[s * DIM + d] * q * 1.4426950408889634f;
        }
    }
}

// ============================ Kernel 2: stream ============================
__global__ void __launch_bounds__(THREADS, 1) k_stream(const float* __restrict__ memory)
{
    extern __shared__ char smem[];
    const int tid = threadIdx.x, lane = tid & 31, warp = tid >> 5;
    const int c = blockIdx.x;
    const int r0 = (int)(((long long)NMEM * c) / NCTA);
    const int r1 = (int)(((long long)NMEM * (c + 1)) / NCTA);
    const int T  = (r1 - r0 + SROWS - 1) / SROWS;

    const uint32_t sb = smem_u32(smem);
    const uint32_t FULL = sb + BARS, EMPTY = FULL + 24;

    if (tid == 0) {
#pragma unroll
        for (int i = 0; i < NSTG; i++) { mbar_init(FULL + 8 * i, 1); mbar_init(EMPTY + 8 * i, 4); }
    }
    // zero stages (tail rows finite on first use; later reuse masked via w=0)
    for (int i = tid; i < (NSTG * STG_BYTES) / 16; i += THREADS)
        *(float4*)(smem + i * 16) = make_float4(0.f, 0.f, 0.f, 0.f);
    // kT[dim][slot]
    {
        float* kT = (float*)(smem + KT_OFF);
        for (int i = tid; i < DIM * SLOTS; i += THREADS) {
            int dimi = i >> 3, s = i & 7;
            kT[dimi * 8 + s] = g_k[s * DIM + dimi];
        }
    }
    __syncthreads();

    // accumulators (consumers)
    ull acc2[SLOTS][4];
#pragma unroll
    for (int s = 0; s < SLOTS; s++) { acc2[s][0] = acc2[s][1] = acc2[s][2] = acc2[s][3] = 0ull; }
    float lp0 = 0.f, lp1 = 0.f;

    if (warp == 8) {
        // ------- producer: 32 x 2-row (2048B) bulk commands per tile, one per lane -------
        for (int t = 0; t < T; t++) {
            const int st = t % 3;
            if (t >= 3) mbar_wait(EMPTY + 8 * st, (t / 3 - 1) & 1);
            const int ts = r0 + t * SROWS;
            const int rows = (r1 - ts < SROWS) ? (r1 - ts) : SROWS;
            if (lane == 0) mbar_expect_tx(FULL + 8 * st, (uint32_t)rows * 1024u);
            __syncwarp();
            const int row0 = 2 * lane;
            if (row0 < rows) {
                const uint32_t bytes = (rows - row0 >= 2) ? 2048u : 1024u;
                bulk_g2s(sb + st * STG_BYTES + lane * PAIRB,
                         memory + (size_t)(ts + row0) * DIM, bytes, FULL + 8 * st);
            }
        }
    } else {
        // ---------------- consumers: warps 0-3 even tiles, 4-7 odd tiles ----------------
        const int g = warp >> 2, wgl = warp & 3;
        const int rowbase = wgl * 16;
        const uint32_t* kTu = (const uint32_t*)(smem + KT_OFF);
        const uint32_t* bb = kTu + (lane & 3) * 8 + (lane >> 2);
        float* wb = (float*)(smem + WB_OFF + warp * 1024);

        // hoist tile-invariant B fragments into registers (64 regs)
        uint32_t breg0[32], breg1[32];
#pragma unroll
        for (int ks = 0; ks < 32; ks++) { breg0[ks] = bb[ks * 64]; breg1[ks] = bb[ks * 64 + 32]; }

        // per-lane A-fragment base: row rowA = rowbase + (lane>>2); row+8 = +8320B (4 pairs)
        const int rowA = rowbase + (lane >> 2);
        const uint32_t aoff = (uint32_t)((rowA >> 1) * PAIRB + (rowA & 1) * 1024);

        for (int t = g; t < T; t += 2) {
            const int st = t % 3;
            mbar_wait(FULL + 8 * st, (t / 3) & 1);
            const int tstart = r0 + t * SROWS;
            const char* tile = smem + st * STG_BYTES;

            // ---- scores via tf32 HMMA: D[16 rows x 8 slots] ----
            float d0 = 0.f, d1 = 0.f, d2 = 0.f, d3 = 0.f;
            const uint32_t* af = (const uint32_t*)(tile + aoff) + (lane & 3);
#pragma unroll
            for (int ks = 0; ks < 32; ks++) {
                uint32_t a0 = af[ks * 8];
                uint32_t a1 = af[ks * 8 + 2080];      // +8320B = 4 pairs
                uint32_t a2 = af[ks * 8 + 4];
                uint32_t a3 = af[ks * 8 + 2084];
                mma8(d0, d1, d2, d3, a0, a1, a2, a3, breg0[ks], breg1[ks]);
            }
            // ---- exp + mask + stash dup pairs ----
            const int row0 = tstart + rowbase + (lane >> 2);
            const int row1 = row0 + 8;
            float w0 = (row0 < r1) ? ex2f(d0) : 0.f;
            float w1 = (row0 < r1) ? ex2f(d1) : 0.f;
            float w2 = (row1 < r1) ? ex2f(d2) : 0.f;
            float w3 = (row1 < r1) ? ex2f(d3) : 0.f;
            lp0 += w0 + w2;
            lp1 += w1 + w3;
            *(float4*)(wb + (lane >> 2) * 16 + (lane & 3) * 4)       = make_float4(w0, w0, w1, w1);
            *(float4*)(wb + (lane >> 2) * 16 + 128 + (lane & 3) * 4) = make_float4(w2, w2, w3, w3);
            __syncwarp();

            // ---- accumulate: acc2[s] += w[row][s] * x[row][dims of lane] ----
#pragma unroll 2
            for (int r = 0; r < 16; r++) {
                const int rr = rowbase + r;
                const char* xrow = tile + (rr >> 1) * PAIRB + (rr & 1) * 1024;
                ulonglong2 xA = *(const ulonglong2*)(xrow + 16 * lane);
                ulonglong2 xB = *(const ulonglong2*)(xrow + 512 + 16 * lane);
                const float4* wd4 = (const float4*)(wb + r * 16);
#pragma unroll
                for (int j = 0; j < 4; j++) {
                    float4 wp = wd4[j];
                    ull wa, wbp;
                    asm("mov.b64 %0, {%2, %3}; mov.b64 %1, {%4, %5};"
                        : "=l"(wa), "=l"(wbp) : "f"(wp.x), "f"(wp.y), "f"(wp.z), "f"(wp.w));
                    acc2[2 * j][0]     = ffma2(wa, xA.x, acc2[2 * j][0]);
                    acc2[2 * j][1]     = ffma2(wa, xA.y, acc2[2 * j][1]);
                    acc2[2 * j][2]     = ffma2(wa, xB.x, acc2[2 * j][2]);
                    acc2[2 * j][3]     = ffma2(wa, xB.y, acc2[2 * j][3]);
                    acc2[2 * j + 1][0] = ffma2(wbp, xA.x, acc2[2 * j + 1][0]);
                    acc2[2 * j + 1][1] = ffma2(wbp, xA.y, acc2[2 * j + 1][1]);
                    acc2[2 * j + 1][2] = ffma2(wbp, xB.x, acc2[2 * j + 1][2]);
                    acc2[2 * j + 1][3] = ffma2(wbp, xB.y, acc2[2 * j + 1][3]);
                }
            }
            __syncwarp();
            if (lane == 0) mbar_arrive(EMPTY + 8 * st);
        }
    }

    __syncthreads();   // pipeline fully drained — smem reusable
    if (warp < 8) {
        float* dst = (float*)(smem + warp * 8192);
#pragma unroll
        for (int s = 0; s < SLOTS; s++) {
            float2 u0 = unpack2(acc2[s][0]);
            float2 u1 = unpack2(acc2[s][1]);
            float2 u2 = unpack2(acc2[s][2]);
            float2 u3 = unpack2(acc2[s][3]);
            *(float4*)(dst + s * DIM + 4 * lane)       = make_float4(u0.x, u0.y, u1.x, u1.y);
            *(float4*)(dst + s * DIM + 128 + 4 * lane) = make_float4(u2.x, u2.y, u3.x, u3.y);
        }
#pragma unroll
        for (int m = 4; m < 32; m <<= 1) {
            lp0 += __shfl_xor_sync(0xffffffffu, lp0, m);
            lp1 += __shfl_xor_sync(0xffffffffu, lp1, m);
        }
        if (lane < 4) {
            float* lb = (float*)(smem + LB_OFF);
            lb[warp * 8 + 2 * lane]     = lp0;
            lb[warp * 8 + 2 * lane + 1] = lp1;
        }
    }
    __syncthreads();
    for (int e = tid; e < 2048; e += THREADS) {
        float sum = 0.f;
#pragma unroll
        for (int w = 0; w < 8; w++) sum += ((const float*)(smem + w * 8192))[e];
        g_pacc[c * 2048 + e] = sum;
    }
    if (tid < 8) {
        const float* lb = (const float*)(smem + LB_OFF);
        float sum = 0.f;
#pragma unroll
        for (int w = 0; w < 8; w++) sum += lb[w * 8 + tid];
        g_pl[c * 8 + tid] = sum;
    }
}

// ============================ Kernel 3: reduce (p-parallel) ============================
__global__ void k_reduce(const float* __restrict__ heads)
{
    // grid 64 x 256: block handles 32 e-values, 8 p-groups
    const int ei = threadIdx.x & 31, pg = threadIdx.x >> 5;
    const int e = blockIdx.x * 32 + ei;
    const int s = e >> 8;
    float acc = 0.f, l = 0.f;
    for (int p = pg; p < NCTA; p += 8) {
        acc += g_pacc[p * 2048 + e];
        l   += g_pl[p * 8 + s];
    }
    __shared__ float sa[8][32], sl[8];
    sa[pg][ei] = acc;
    if (ei == 0) sl[pg] = l;
    __syncthreads();
    if (pg == 0) {
        float a = 0.f, lt = 0.f;
#pragma unroll
        for (int g = 0; g < 8; g++) { a += sa[g][ei]; lt += sl[g]; }
        float raw = a / lt;
        float q = g_qspace[e];
        g_newheads[e] = raw * q + (1.f - q) * heads[e];
    }
}

// ============================ Kernel 4: synth (warp-per-output) ============================
__global__ void __launch_bounds__(1024) k_synth(const float* __restrict__ state,
                                                const float* __restrict__ sW,
                                                const float* __restrict__ sb)
{
    const int i = (blockIdx.x * 1024 + threadIdx.x) >> 5;   // 0..255
    const int lane = threadIdx.x & 31;
    const float4* w4 = (const float4*)(sW + (size_t)i * (DIM * (SLOTS + 1)));
    float p = 0.f;
#pragma unroll
    for (int it = 0; it < 18; it++) {
        int j4 = lane + it * 32;
        float4 w = w4[j4];
        float4 cv = (j4 < DIM / 4) ? *(const float4*)(state + 4 * j4)
                                   : *(const float4*)(g_newheads + 4 * j4 - DIM);
        p += w.x * cv.x + w.y * cv.y + w.z * cv.z + w.w * cv.w;
    }
#pragma unroll
    for (int m = 16; m >= 1; m >>= 1) p += __shfl_xor_sync(0xffffffffu, p, m);
    if (lane == 0) g_newstate[i] = p + sb[i];
}

// ============================ Kernel 5: out ============================
__global__ void k_out(const float* __restrict__ rvW, const float* __restrict__ rvb,
                      float* __restrict__ out)
{
    const int t = threadIdx.x;
    float ns = g_newstate[t];
    __shared__ float sm[256];
    sm[t] = ns * rvW[t];
    __syncthreads();
    for (int off = 128; off > 0; off >>= 1) { if (t < off) sm[t] += sm[t + off]; __syncthreads(); }
    __shared__ float rev;
    if (t == 0) rev = 1.f / (1.f + __expf(-(sm[0] + rvb[0])));
    __syncthreads();
    out[t] = ns * rev;
}

// ===================================================================================
extern "C" void kernel_launch(void* const* d_in, const int* in_sizes, int n_in,
                              void* d_out, int out_size)
{
    const float* memory = (const float*)d_in[0];
    const float* heads  = (const float*)d_in[1];
    const float* state  = (const float*)d_in[2];
    const float* qW     = (const float*)d_in[3];
    const float* qb     = (const float*)d_in[4];
    const float* sW     = (const float*)d_in[5];
    const float* sb     = (const float*)d_in[6];
    const float* rvW    = (const float*)d_in[7];
    const float* rvb    = (const float*)d_in[8];
    float* out = (float*)d_out;

    cudaFuncSetAttribute(k_stream, cudaFuncAttributeMaxDynamicSharedMemorySize, DYN_SMEM);

    k_setup<<<8, 1024>>>(heads, state, qW, qb);
    k_stream<<<NCTA, THREADS, DYN_SMEM>>>(memory);
    k_reduce<<<64, 256>>>(heads);
    k_synth<<<8, 1024>>>(state, sW, sb);
    k_out<<<1, 256>>>(rvW, rvb, out);
}

// round 14
// speedup vs baseline: 2.0322x; 1.0577x over previous
#include <cuda_runtime.h>
#include <cstdint>

#define DIM       256
#define SLOTS     8
#define NMEM      1000000
#define NCTA      148
#define THREADS   288                 // 9 warps: 0-7 consumers, 8 producer
#define SROWS     64                  // rows per stage/tile (32 pairs)
#define PAIRB     2064                // 2 rows (2048B) + 16B pad  (516 words ≡ 4 mod 32)
#define STG_BYTES (32 * PAIRB)        // 66048
#define NSTG      3
#define KT_OFF    (NSTG * STG_BYTES)  // 198144 : kT[dim][slot] 8KB
#define WB_OFF    (KT_OFF + 8192)     // 206336 : per-warp w scratch 8 x 1KB
#define LB_OFF    (WB_OFF + 8192)     // 214528 : l partials 256B
#define BARS      (LB_OFF + 256)      // 214784
#define DYN_SMEM  (BARS + 64)         // 214848

typedef unsigned long long ull;

__device__ __align__(256) float g_k[SLOTS * DIM];          // heads*qspace*log2(e)
__device__ __align__(256) float g_qspace[SLOTS * DIM];
__device__ __align__(256) float g_pacc[NCTA * SLOTS * DIM];
__device__ __align__(256) float g_pl[NCTA * SLOTS];
__device__ __align__(256) float g_newheads[SLOTS * DIM];
__device__ __align__(256) float g_newstate[DIM];

__device__ __forceinline__ ull ffma2(ull a, ull b, ull c) {
    ull d; asm("fma.rn.f32x2 %0, %1, %2, %3;" : "=l"(d) : "l"(a), "l"(b), "l"(c)); return d;
}
__device__ __forceinline__ float2 unpack2(ull v) {
    float2 f; asm("mov.b64 {%0, %1}, %2;" : "=f"(f.x), "=f"(f.y) : "l"(v)); return f;
}
__device__ __forceinline__ float ex2f(float x) {
    float r; asm("ex2.approx.f32 %0, %1;" : "=f"(r) : "f"(x)); return r;
}
__device__ __forceinline__ uint32_t smem_u32(const void* p) {
    uint32_t a; asm("{ .reg .u64 t; cvta.to.shared.u64 t, %1; cvt.u32.u64 %0, t; }" : "=r"(a) : "l"(p)); return a;
}
__device__ __forceinline__ void mbar_init(uint32_t a, uint32_t c) {
    asm volatile("mbarrier.init.shared.b64 [%0], %1;" :: "r"(a), "r"(c) : "memory");
}
__device__ __forceinline__ void mbar_arrive(uint32_t a) {
    asm volatile("mbarrier.arrive.release.cta.shared::cta.b64 _, [%0];" :: "r"(a) : "memory");
}
__device__ __forceinline__ void mbar_expect_tx(uint32_t a, uint32_t bytes) {
    asm volatile("mbarrier.arrive.expect_tx.shared.b64 _, [%0], %1;" :: "r"(a), "r"(bytes) : "memory");
}
__device__ __forceinline__ void mbar_wait(uint32_t a, uint32_t par) {
    asm volatile(
        "{\n\t.reg .pred P;\nWL%=:\n\t"
        "mbarrier.try_wait.parity.acquire.cta.shared::cta.b64 P, [%0], %1, 0x989680;\n\t"
        "@P bra.uni WD%=;\n\tbra.uni WL%=;\nWD%=:\n\t}" :: "r"(a), "r"(par) : "memory");
}
__device__ __forceinline__ void bulk_g2s(uint32_t dst, const void* src, uint32_t bytes, uint32_t mbar) {
    asm volatile("cp.async.bulk.shared::cta.global.mbarrier::complete_tx::bytes [%0], [%1], %2, [%3];"
                 :: "r"(dst), "l"(src), "r"(bytes), "r"(mbar) : "memory");
}
// m16n8k8 tf32 HMMA, raw f32 bits as tf32
__device__ __forceinline__ void mma8(float& d0, float& d1, float& d2, float& d3,
                                     uint32_t a0, uint32_t a1, uint32_t a2, uint32_t a3,
                                     uint32_t b0, uint32_t b1) {
    asm volatile("mma.sync.aligned.m16n8k8.row.col.f32.tf32.tf32.f32 "
                 "{%0,%1,%2,%3}, {%4,%5,%6,%7}, {%8,%9}, {%0,%1,%2,%3};"
                 : "+f"(d0), "+f"(d1), "+f"(d2), "+f"(d3)
                 : "r"(a0), "r"(a1), "r"(a2), "r"(a3), "r"(b0), "r"(b1));
}

// ============================ Kernel 1: setup (warp-per-d, 64 blocks) ============================
__global__ void __launch_bounds__(128) k_setup(const float* __restrict__ heads,
                                               const float* __restrict__ state,
                                               const float* __restrict__ qW,
                                               const float* __restrict__ qb)
{
    const int d = blockIdx.x * 4 + (threadIdx.x >> 5);   // 0..255
    const int lane = threadIdx.x & 31;
    float pc = 0.f, ps[SLOTS];
#pragma unroll
    for (int s = 0; s < SLOTS; s++) ps[s] = 0.f;
    const float* wrow = qW + (size_t)d * (2 * DIM);
#pragma unroll
    for (int it = 0; it < 8; it++) {
        int j = lane + it * 32;
        pc += wrow[j] * state[j];
    }
#pragma unroll
    for (int it = 0; it < 8; it++) {
        int jj = lane + it * 32;
        float w = wrow[DIM + jj];
#pragma unroll
        for (int s = 0; s < SLOTS; s++) ps[s] += w * heads[s * DIM + jj];
    }
#pragma unroll
    for (int m = 16; m >= 1; m >>= 1) {
        pc += __shfl_xor_sync(0xffffffffu, pc, m);
#pragma unroll
        for (int s = 0; s < SLOTS; s++) ps[s] += __shfl_xor_sync(0xffffffffu, ps[s], m);
    }
    if (lane == 0) {
        float b = qb[d];
#pragma unroll
        for (int s = 0; s < SLOTS; s++) {
            float q = tanhf(ps[s] + pc + b);
            g_qspace[s * DIM + d] = q;
            g_k[s * DIM + d] = heads[s * DIM + d] * q * 1.4426950408889634f;
        }
    }
}

// ============================ Kernel 2: stream ============================
__global__ void __launch_bounds__(THREADS, 1) k_stream(const float* __restrict__ memory)
{
    extern __shared__ char smem[];
    const int tid = threadIdx.x, lane = tid & 31, warp = tid >> 5;
    const int c = blockIdx.x;
    const int r0 = (int)(((long long)NMEM * c) / NCTA);
    const int r1 = (int)(((long long)NMEM * (c + 1)) / NCTA);
    const int T  = (r1 - r0 + SROWS - 1) / SROWS;

    const uint32_t sb = smem_u32(smem);
    const uint32_t FULL = sb + BARS, EMPTY = FULL + 24;

    if (tid == 0) {
#pragma unroll
        for (int i = 0; i < NSTG; i++) { mbar_init(FULL + 8 * i, 1); mbar_init(EMPTY + 8 * i, 4); }
    }
    // zero stages (tail rows finite on first use; later reuse masked via w=0)
    for (int i = tid; i < (NSTG * STG_BYTES) / 16; i += THREADS)
        *(float4*)(smem + i * 16) = make_float4(0.f, 0.f, 0.f, 0.f);
    // kT[dim][slot]
    {
        float* kT = (float*)(smem + KT_OFF);
        for (int i = tid; i < DIM * SLOTS; i += THREADS) {
            int dimi = i >> 3, s = i & 7;
            kT[dimi * 8 + s] = g_k[s * DIM + dimi];
        }
    }
    __syncthreads();

    // accumulators (consumers)
    ull acc2[SLOTS][4];
#pragma unroll
    for (int s = 0; s < SLOTS; s++) { acc2[s][0] = acc2[s][1] = acc2[s][2] = acc2[s][3] = 0ull; }
    float lp0 = 0.f, lp1 = 0.f;

    if (warp == 8) {
        // ------- producer: 32 x 2-row (2048B) bulk commands per tile, one per lane -------
        for (int t = 0; t < T; t++) {
            const int st = t % 3;
            if (t >= 3) mbar_wait(EMPTY + 8 * st, (t / 3 - 1) & 1);
            const int ts = r0 + t * SROWS;
            const int rows = (r1 - ts < SROWS) ? (r1 - ts) : SROWS;
            if (lane == 0) mbar_expect_tx(FULL + 8 * st, (uint32_t)rows * 1024u);
            __syncwarp();
            const int row0 = 2 * lane;
            if (row0 < rows) {
                const uint32_t bytes = (rows - row0 >= 2) ? 2048u : 1024u;
                bulk_g2s(sb + st * STG_BYTES + lane * PAIRB,
                         memory + (size_t)(ts + row0) * DIM, bytes, FULL + 8 * st);
            }
        }
    } else {
        // ---------------- consumers: warps 0-3 even tiles, 4-7 odd tiles ----------------
        // Logical MMA rows 0-7 -> pair-row0 of the warp's 8 pairs; 8-15 -> pair-row1.
        const int g = warp >> 2, wgl = warp & 3;
        const int rowbase = wgl * 16;                 // 16 physical rows = pairs wgl*8 .. wgl*8+7
        const uint32_t* kTu = (const uint32_t*)(smem + KT_OFF);
        const uint32_t* bb = kTu + (lane & 3) * 8 + (lane >> 2);
        float* wb = (float*)(smem + WB_OFF + warp * 1024);

        // hoist tile-invariant B fragments into registers (64 regs)
        uint32_t breg0[32], breg1[32];
#pragma unroll
        for (int ks = 0; ks < 32; ks++) { breg0[ks] = bb[ks * 64]; breg1[ks] = bb[ks * 64 + 32]; }

        // A-fragment base: logical row lane>>2 -> pair (wgl*8 + (lane>>2)), row0
        const uint32_t aoff = (uint32_t)((wgl * 8 + (lane >> 2)) * PAIRB);

        for (int t = g; t < T; t += 2) {
            const int st = t % 3;
            mbar_wait(FULL + 8 * st, (t / 3) & 1);
            const int tstart = r0 + t * SROWS;
            const char* tile = smem + st * STG_BYTES;

            // ---- scores via tf32 HMMA: D[16 rows x 8 slots] (conflict-free A loads) ----
            float d0 = 0.f, d1 = 0.f, d2 = 0.f, d3 = 0.f;
            const uint32_t* af = (const uint32_t*)(tile + aoff) + (lane & 3);
#pragma unroll
            for (int ks = 0; ks < 32; ks++) {
                uint32_t a0 = af[ks * 8];
                uint32_t a1 = af[ks * 8 + 256];   // +1024B = pair row1
                uint32_t a2 = af[ks * 8 + 4];
                uint32_t a3 = af[ks * 8 + 260];
                mma8(d0, d1, d2, d3, a0, a1, a2, a3, breg0[ks], breg1[ks]);
            }
            // ---- exp + mask + stash dup pairs (physical rows: d0/d1 -> even, d2/d3 -> odd) ----
            const int pr0 = 2 * (lane >> 2);          // physical local row for d0/d1
            const int row0 = tstart + rowbase + pr0;
            const int row1 = row0 + 1;
            float w0 = (row0 < r1) ? ex2f(d0) : 0.f;
            float w1 = (row0 < r1) ? ex2f(d1) : 0.f;
            float w2 = (row1 < r1) ? ex2f(d2) : 0.f;
            float w3 = (row1 < r1) ? ex2f(d3) : 0.f;
            lp0 += w0 + w2;
            lp1 += w1 + w3;
            *(float4*)(wb + pr0 * 16 + (lane & 3) * 4)        = make_float4(w0, w0, w1, w1);
            *(float4*)(wb + (pr0 + 1) * 16 + (lane & 3) * 4)  = make_float4(w2, w2, w3, w3);
            __syncwarp();

            // ---- accumulate: acc2[s] += w[row][s] * x[row][dims of lane] ----
#pragma unroll 2
            for (int r = 0; r < 16; r++) {
                const char* xrow = tile + (wgl * 8 + (r >> 1)) * PAIRB + (r & 1) * 1024;
                ulonglong2 xA = *(const ulonglong2*)(xrow + 16 * lane);
                ulonglong2 xB = *(const ulonglong2*)(xrow + 512 + 16 * lane);
                const float4* wd4 = (const float4*)(wb + r * 16);
#pragma unroll
                for (int j = 0; j < 4; j++) {
                    float4 wp = wd4[j];
                    ull wa, wbp;
                    asm("mov.b64 %0, {%2, %3}; mov.b64 %1, {%4, %5};"
                        : "=l"(wa), "=l"(wbp) : "f"(wp.x), "f"(wp.y), "f"(wp.z), "f"(wp.w));
                    acc2[2 * j][0]     = ffma2(wa, xA.x, acc2[2 * j][0]);
                    acc2[2 * j][1]     = ffma2(wa, xA.y, acc2[2 * j][1]);
                    acc2[2 * j][2]     = ffma2(wa, xB.x, acc2[2 * j][2]);
                    acc2[2 * j][3]     = ffma2(wa, xB.y, acc2[2 * j][3]);
                    acc2[2 * j + 1][0] = ffma2(wbp, xA.x, acc2[2 * j + 1][0]);
                    acc2[2 * j + 1][1] = ffma2(wbp, xA.y, acc2[2 * j + 1][1]);
                    acc2[2 * j + 1][2] = ffma2(wbp, xB.x, acc2[2 * j + 1][2]);
                    acc2[2 * j + 1][3] = ffma2(wbp, xB.y, acc2[2 * j + 1][3]);
                }
            }
            __syncwarp();
            if (lane == 0) mbar_arrive(EMPTY + 8 * st);
        }
    }

    __syncthreads();   // pipeline fully drained — smem reusable
    if (warp < 8) {
        float* dst = (float*)(smem + warp * 8192);
#pragma unroll
        for (int s = 0; s < SLOTS; s++) {
            float2 u0 = unpack2(acc2[s][0]);
            float2 u1 = unpack2(acc2[s][1]);
            float2 u2 = unpack2(acc2[s][2]);
            float2 u3 = unpack2(acc2[s][3]);
            *(float4*)(dst + s * DIM + 4 * lane)       = make_float4(u0.x, u0.y, u1.x, u1.y);
            *(float4*)(dst + s * DIM + 128 + 4 * lane) = make_float4(u2.x, u2.y, u3.x, u3.y);
        }
#pragma unroll
        for (int m = 4; m < 32; m <<= 1) {
            lp0 += __shfl_xor_sync(0xffffffffu, lp0, m);
            lp1 += __shfl_xor_sync(0xffffffffu, lp1, m);
        }
        if (lane < 4) {
            float* lb = (float*)(smem + LB_OFF);
            lb[warp * 8 + 2 * lane]     = lp0;
            lb[warp * 8 + 2 * lane + 1] = lp1;
        }
    }
    __syncthreads();
    for (int e = tid; e < 2048; e += THREADS) {
        float sum = 0.f;
#pragma unroll
        for (int w = 0; w < 8; w++) sum += ((const float*)(smem + w * 8192))[e];
        g_pacc[c * 2048 + e] = sum;
    }
    if (tid < 8) {
        const float* lb = (const float*)(smem + LB_OFF);
        float sum = 0.f;
#pragma unroll
        for (int w = 0; w < 8; w++) sum += lb[w * 8 + tid];
        g_pl[c * 8 + tid] = sum;
    }
}

// ============================ Kernel 3: reduce (p-parallel) ============================
__global__ void k_reduce(const float* __restrict__ heads)
{
    // grid 64 x 256: block handles 32 e-values, 8 p-groups
    const int ei = threadIdx.x & 31, pg = threadIdx.x >> 5;
    const int e = blockIdx.x * 32 + ei;
    const int s = e >> 8;
    float acc = 0.f, l = 0.f;
    for (int p = pg; p < NCTA; p += 8) {
        acc += g_pacc[p * 2048 + e];
        l   += g_pl[p * 8 + s];
    }
    __shared__ float sa[8][32], sl[8];
    sa[pg][ei] = acc;
    if (ei == 0) sl[pg] = l;
    __syncthreads();
    if (pg == 0) {
        float a = 0.f, lt = 0.f;
#pragma unroll
        for (int g = 0; g < 8; g++) { a += sa[g][ei]; lt += sl[g]; }
        float raw = a / lt;
        float q = g_qspace[e];
        g_newheads[e] = raw * q + (1.f - q) * heads[e];
    }
}

// ============================ Kernel 4: synth (warp-per-output, 64 blocks) ============================
__global__ void __launch_bounds__(128) k_synth(const float* __restrict__ state,
                                               const float* __restrict__ sW,
                                               const float* __restrict__ sb)
{
    const int i = blockIdx.x * 4 + (threadIdx.x >> 5);   // 0..255
    const int lane = threadIdx.x & 31;
    const float4* w4 = (const float4*)(sW + (size_t)i * (DIM * (SLOTS + 1)));
    float p = 0.f;
#pragma unroll
    for (int it = 0; it < 18; it++) {
        int j4 = lane + it * 32;
        float4 w = w4[j4];
        float4 cv = (j4 < DIM / 4) ? *(const float4*)(state + 4 * j4)
                                   : *(const float4*)(g_newheads + 4 * j4 - DIM);
        p += w.x * cv.x + w.y * cv.y + w.z * cv.z + w.w * cv.w;
    }
#pragma unroll
    for (int m = 16; m >= 1; m >>= 1) p += __shfl_xor_sync(0xffffffffu, p, m);
    if (lane == 0) g_newstate[i] = p + sb[i];
}

// ============================ Kernel 5: out ============================
__global__ void k_out(const float* __restrict__ rvW, const float* __restrict__ rvb,
                      float* __restrict__ out)
{
    const int t = threadIdx.x;
    float ns = g_newstate[t];
    __shared__ float sm[256];
    sm[t] = ns * rvW[t];
    __syncthreads();
    for (int off = 128; off > 0; off >>= 1) { if (t < off) sm[t] += sm[t + off]; __syncthreads(); }
    __shared__ float rev;
    if (t == 0) rev = 1.f / (1.f + __expf(-(sm[0] + rvb[0])));
    __syncthreads();
    out[t] = ns * rev;
}

// ===================================================================================
extern "C" void kernel_launch(void* const* d_in, const int* in_sizes, int n_in,
                              void* d_out, int out_size)
{
    const float* memory = (const float*)d_in[0];
    const float* heads  = (const float*)d_in[1];
    const float* state  = (const float*)d_in[2];
    const float* qW     = (const float*)d_in[3];
    const float* qb     = (const float*)d_in[4];
    const float* sW     = (const float*)d_in[5];
    const float* sb     = (const float*)d_in[6];
    const float* rvW    = (const float*)d_in[7];
    const float* rvb    = (const float*)d_in[8];
    float* out = (float*)d_out;

    cudaFuncSetAttribute(k_stream, cudaFuncAttributeMaxDynamicSharedMemorySize, DYN_SMEM);

    k_setup<<<64, 128>>>(heads, state, qW, qb);
    k_stream<<<NCTA, THREADS, DYN_SMEM>>>(memory);
    k_reduce<<<64, 256>>>(heads);
    k_synth<<<64, 128>>>(state, sW, sb);
    k_out<<<1, 256>>>(rvW, rvb, out);
}